// round 13
// baseline (speedup 1.0000x reference)
#include <cuda_runtime.h>
#include <cuda_fp16.h>
#include <math.h>
#include <stdint.h>

#define NN 50000
#define NE 800000
#define DHID 128
#define NH 4
#define DHEAD 32
#define OUTD 512
#define NEG_SLOPE 0.2f
#define EPSV 1e-9f

#define SPLIT 25024   // divisible by 8 and 64

// GEMM smem layout (floats): 3 stages A[64][20] + 3 stages B[16][132]
#define A_STRIDE 20
#define B_STRIDE 132
#define A_STAGE (64 * A_STRIDE)
#define B_STAGE (16 * B_STRIDE)
#define SMEM_FLOATS (3 * A_STAGE + 3 * B_STAGE)
#define SMEM_BYTES (SMEM_FLOATS * 4)      // 40704

// ---------------- scratch (device globals; no allocation) ----------------
__device__ __half g_Whh[NN * DHID];
__device__ float g_z[NN * DHID];      // tf32-rounded
__device__ float g_el[NN * NH];
__device__ float g_er[NN * NH];
__device__ float g_z2[NN * DHEAD];    // tf32-rounded
__device__ int   g_cnt[NN];
__device__ int   g_rowptr[NN + 1];
__device__ int   g_epos[NE];
__device__ int   g_csrc[NE];
__device__ float g_W1t[DHID * DHID];
__device__ float g_W2t[DHID * DHID];
__device__ float g_Wpt[DHEAD * OUTD];

__device__ __forceinline__ float lrelu(float x) {
    return x > 0.0f ? x : NEG_SLOPE * x;
}

__device__ __forceinline__ uint32_t f2tf32(float x) {
    uint32_t u;
    asm("cvt.rna.tf32.f32 %0, %1;" : "=r"(u) : "f"(x));
    return u;
}

__device__ __forceinline__ float round_tf32(float x) {
    return __uint_as_float(f2tf32(x));
}

__device__ __forceinline__ void mma_tf32(float* c, const uint32_t* a, const uint32_t* b) {
    asm volatile(
        "mma.sync.aligned.m16n8k8.row.col.f32.tf32.tf32.f32 "
        "{%0,%1,%2,%3}, {%4,%5,%6,%7}, {%8,%9}, {%0,%1,%2,%3};"
        : "+f"(c[0]), "+f"(c[1]), "+f"(c[2]), "+f"(c[3])
        : "r"(a[0]), "r"(a[1]), "r"(a[2]), "r"(a[3]), "r"(b[0]), "r"(b[1]));
}

__device__ __forceinline__ uint32_t su(const void* p) {
    return (uint32_t)__cvta_generic_to_shared(p);
}

__device__ __forceinline__ void cp16(uint32_t dst, const void* src, bool p) {
    int sz = p ? 16 : 0;
    asm volatile("cp.async.cg.shared.global [%0], [%1], 16, %2;"
                 :: "r"(dst), "l"(src), "r"(sz));
}

// ============ weight pre-rounding ====
__global__ void k_round_w1(const float* __restrict__ W1) {
    int i = blockIdx.x * blockDim.x + threadIdx.x;   // 0..16383
    if (i < DHID * DHID) g_W1t[i] = round_tf32(W1[i]);
}
__global__ void k_round_w2p(const float* __restrict__ W2, const float* __restrict__ Wp) {
    int i = blockIdx.x * blockDim.x + threadIdx.x;   // 0..32767
    if (i < 16384) g_W2t[i] = round_tf32(W2[i]);
    else if (i < 32768) g_Wpt[i - 16384] = round_tf32(Wp[i - 16384]);
}

// ================= tensor-core GEMM (tf32 mma.sync) =================
// Block tile 64x128, 8 warps (2m x 4n), 3-stage cp.async.
// CVTA: cvt A fragments at load (else A pre-rounded). B always pre-rounded.
// FUSE=1: writes fp16 g_Whh + g_el/g_er (grid.x==1, N==128); no fp32 C.
// FUSE=0: writes fp32 C (+bias).  rowOff = row offset of this launch.
template <int FUSE, int CVTA>
__global__ void __launch_bounds__(256, 3)
gemm_tc(const float* __restrict__ A, const float* __restrict__ B,
        const float* __restrict__ bias, float* __restrict__ C,
        int M, int N, int K,
        const float* __restrict__ al, const float* __restrict__ ar,
        int rowOff) {
    extern __shared__ float smem[];

    const int tid = threadIdx.x;
    const int wid = tid >> 5, lane = tid & 31;
    const int g = lane >> 2, t = lane & 3;
    const int wm = wid & 1;
    const int wn = wid >> 1;
    const int rowBase = rowOff + blockIdx.y * 64;
    const int colBase = blockIdx.x * 128;

    const int aRow = tid >> 2, aK0 = (tid & 3) * 4;
    const int bK0 = tid >> 5, bN0 = (tid & 31) * 4;
    const bool ap = (rowBase + aRow) < M;
    const float* aSrc = A + (size_t)(ap ? rowBase + aRow : 0) * K + aK0;
    const float* bSrc0 = B + (size_t)bK0 * N + colBase + bN0;
    const float* bSrc1 = B + (size_t)(bK0 + 8) * N + colBase + bN0;

    float acc[2][4][4];
#pragma unroll
    for (int mf = 0; mf < 2; mf++)
#pragma unroll
        for (int nf = 0; nf < 4; nf++)
#pragma unroll
            for (int r = 0; r < 4; r++) acc[mf][nf][r] = 0.0f;

    const int nStages = K >> 4;

    uint32_t aDst = su(smem + aRow * A_STRIDE + aK0);
    uint32_t bDst0 = su(smem + 3 * A_STAGE + bK0 * B_STRIDE + bN0);
    uint32_t bDst1 = su(smem + 3 * A_STAGE + (bK0 + 8) * B_STRIDE + bN0);

#pragma unroll
    for (int s = 0; s < 2; s++) {
        int k0g = s * 16;
        cp16(aDst + s * A_STAGE * 4, aSrc + k0g, ap);
        cp16(bDst0 + s * B_STAGE * 4, bSrc0 + (size_t)k0g * N, true);
        cp16(bDst1 + s * B_STAGE * 4, bSrc1 + (size_t)k0g * N, true);
        asm volatile("cp.async.commit_group;");
    }

    for (int st = 0; st < nStages; st++) {
        if (nStages - st >= 2) asm volatile("cp.async.wait_group 1;" ::: "memory");
        else                   asm volatile("cp.async.wait_group 0;" ::: "memory");
        __syncthreads();

        const int cur = st % 3;
        const float* Asf = smem + cur * A_STAGE;
        const float* Bsf = smem + 3 * A_STAGE + cur * B_STAGE;

#pragma unroll
        for (int kk = 0; kk < 2; kk++) {
            const int k0 = kk * 8;
            uint32_t af[2][4], bf[4][2];
#pragma unroll
            for (int mf = 0; mf < 2; mf++) {
                int r0 = wm * 32 + mf * 16 + g;
                float a0 = Asf[r0 * A_STRIDE + k0 + t];
                float a1 = Asf[(r0 + 8) * A_STRIDE + k0 + t];
                float a2 = Asf[r0 * A_STRIDE + k0 + t + 4];
                float a3 = Asf[(r0 + 8) * A_STRIDE + k0 + t + 4];
                if (CVTA) {
                    af[mf][0] = f2tf32(a0); af[mf][1] = f2tf32(a1);
                    af[mf][2] = f2tf32(a2); af[mf][3] = f2tf32(a3);
                } else {
                    af[mf][0] = __float_as_uint(a0); af[mf][1] = __float_as_uint(a1);
                    af[mf][2] = __float_as_uint(a2); af[mf][3] = __float_as_uint(a3);
                }
            }
#pragma unroll
            for (int nf = 0; nf < 4; nf++) {
                int n0 = wn * 32 + nf * 8 + g;
                bf[nf][0] = __float_as_uint(Bsf[(k0 + t) * B_STRIDE + n0]);
                bf[nf][1] = __float_as_uint(Bsf[(k0 + t + 4) * B_STRIDE + n0]);
            }
#pragma unroll
            for (int mf = 0; mf < 2; mf++)
#pragma unroll
                for (int nf = 0; nf < 4; nf++)
                    mma_tf32(acc[mf][nf], af[mf], bf[nf]);
        }

        if (st + 2 < nStages) {
            int s = (st + 2) % 3;
            int k0g = (st + 2) * 16;
            cp16(aDst + s * A_STAGE * 4, aSrc + k0g, ap);
            cp16(bDst0 + s * B_STAGE * 4, bSrc0 + (size_t)k0g * N, true);
            cp16(bDst1 + s * B_STAGE * 4, bSrc1 + (size_t)k0g * N, true);
            asm volatile("cp.async.commit_group;");
        }
    }

    if (!FUSE) {
#pragma unroll
        for (int mf = 0; mf < 2; mf++) {
            int row0 = rowBase + wm * 32 + mf * 16 + g;
#pragma unroll
            for (int nf = 0; nf < 4; nf++) {
                int col = colBase + wn * 32 + nf * 8 + 2 * t;
                float b0 = bias ? bias[col] : 0.f;
                float b1 = bias ? bias[col + 1] : 0.f;
                if (row0 < M) {
                    float2 v = make_float2(acc[mf][nf][0] + b0, acc[mf][nf][1] + b1);
                    *(float2*)(C + (size_t)row0 * N + col) = v;
                }
                if (row0 + 8 < M) {
                    float2 v = make_float2(acc[mf][nf][2] + b0, acc[mf][nf][3] + b1);
                    *(float2*)(C + (size_t)(row0 + 8) * N + col) = v;
                }
            }
        }
    } else {
        float elp[2][2] = {}, erp[2][2] = {};
#pragma unroll
        for (int nf = 0; nf < 4; nf++) {
            int col = wn * 32 + nf * 8 + 2 * t;
            float la0 = al[col], la1 = al[col + 1];
            float ra0 = ar[col], ra1 = ar[col + 1];
#pragma unroll
            for (int mf = 0; mf < 2; mf++) {
                elp[mf][0] += acc[mf][nf][0] * la0 + acc[mf][nf][1] * la1;
                elp[mf][1] += acc[mf][nf][2] * la0 + acc[mf][nf][3] * la1;
                erp[mf][0] += acc[mf][nf][0] * ra0 + acc[mf][nf][1] * ra1;
                erp[mf][1] += acc[mf][nf][2] * ra0 + acc[mf][nf][3] * ra1;
                int row0 = rowBase + wm * 32 + mf * 16 + g;
                if (row0 < M) {
                    __half2 hv = __floats2half2_rn(acc[mf][nf][0], acc[mf][nf][1]);
                    *(__half2*)(g_Whh + (size_t)row0 * DHID + col) = hv;
                }
                if (row0 + 8 < M) {
                    __half2 hv = __floats2half2_rn(acc[mf][nf][2], acc[mf][nf][3]);
                    *(__half2*)(g_Whh + (size_t)(row0 + 8) * DHID + col) = hv;
                }
            }
        }
#pragma unroll
        for (int mf = 0; mf < 2; mf++)
#pragma unroll
            for (int rh = 0; rh < 2; rh++) {
                float v = elp[mf][rh];
                v += __shfl_xor_sync(0xFFFFFFFFu, v, 1);
                v += __shfl_xor_sync(0xFFFFFFFFu, v, 2);
                elp[mf][rh] = v;
                float w = erp[mf][rh];
                w += __shfl_xor_sync(0xFFFFFFFFu, w, 1);
                w += __shfl_xor_sync(0xFFFFFFFFu, w, 2);
                erp[mf][rh] = w;
            }
        if (t == 0) {
#pragma unroll
            for (int mf = 0; mf < 2; mf++)
#pragma unroll
                for (int rh = 0; rh < 2; rh++) {
                    int gr = rowBase + wm * 32 + mf * 16 + g + rh * 8;
                    if (gr < M) {
                        g_el[gr * NH + wn] = elp[mf][rh];
                        g_er[gr * NH + wn] = erp[mf][rh];
                    }
                }
        }
    }
}

// ---------------- streams/events + func attrs ----------------
static cudaStream_t g_s2, g_s3;
static cudaEvent_t g_evFork, g_evCsr, g_evW1, g_evW2p, g_evA2a, g_evP1;
struct HostInit {
    HostInit() {
        cudaStreamCreateWithFlags(&g_s2, cudaStreamNonBlocking);
        cudaStreamCreateWithFlags(&g_s3, cudaStreamNonBlocking);
        cudaEventCreateWithFlags(&g_evFork, cudaEventDisableTiming);
        cudaEventCreateWithFlags(&g_evCsr, cudaEventDisableTiming);
        cudaEventCreateWithFlags(&g_evW1, cudaEventDisableTiming);
        cudaEventCreateWithFlags(&g_evW2p, cudaEventDisableTiming);
        cudaEventCreateWithFlags(&g_evA2a, cudaEventDisableTiming);
        cudaEventCreateWithFlags(&g_evP1, cudaEventDisableTiming);
        cudaFuncSetAttribute((const void*)gemm_tc<0, 0>, cudaFuncAttributeMaxDynamicSharedMemorySize, SMEM_BYTES);
        cudaFuncSetAttribute((const void*)gemm_tc<1, 0>, cudaFuncAttributeMaxDynamicSharedMemorySize, SMEM_BYTES);
        cudaFuncSetAttribute((const void*)gemm_tc<1, 1>, cudaFuncAttributeMaxDynamicSharedMemorySize, SMEM_BYTES);
    }
};
static HostInit g_hostInit;

// ================= CSR build (8 edges/thread, epos-based) =================
__global__ void k_count(const int4* __restrict__ dst4) {
    int i = blockIdx.x * blockDim.x + threadIdx.x;
    if (i >= NE / 8) return;
    int4 d0 = dst4[2 * i], d1 = dst4[2 * i + 1];
    int4 p0, p1;
    p0.x = atomicAdd(&g_cnt[d0.x], 1);
    p0.y = atomicAdd(&g_cnt[d0.y], 1);
    p0.z = atomicAdd(&g_cnt[d0.z], 1);
    p0.w = atomicAdd(&g_cnt[d0.w], 1);
    p1.x = atomicAdd(&g_cnt[d1.x], 1);
    p1.y = atomicAdd(&g_cnt[d1.y], 1);
    p1.z = atomicAdd(&g_cnt[d1.z], 1);
    p1.w = atomicAdd(&g_cnt[d1.w], 1);
    ((int4*)g_epos)[2 * i] = p0;
    ((int4*)g_epos)[2 * i + 1] = p1;
}

__global__ void k_scan() {
    __shared__ int warpsum[32];
    const int T = 1024;
    const int CH = (NN + T - 1) / T;
    int t = threadIdx.x;
    int lane = t & 31, wid = t >> 5;
    int lo = t * CH;
    int hi = lo + CH; if (hi > NN) hi = NN;
    if (lo > NN) lo = NN;
    int s = 0;
    for (int i = lo; i < hi; i++) s += g_cnt[i];
    int v = s;
#pragma unroll
    for (int o = 1; o < 32; o <<= 1) {
        int u = __shfl_up_sync(0xFFFFFFFFu, v, o);
        if (lane >= o) v += u;
    }
    if (lane == 31) warpsum[wid] = v;
    __syncthreads();
    if (wid == 0) {
        int w = warpsum[lane];
#pragma unroll
        for (int o = 1; o < 32; o <<= 1) {
            int u = __shfl_up_sync(0xFFFFFFFFu, w, o);
            if (lane >= o) w += u;
        }
        warpsum[lane] = w;
    }
    __syncthreads();
    int excl = v - s + (wid > 0 ? warpsum[wid - 1] : 0);
    int run = excl;
    for (int i = lo; i < hi; i++) {
        g_rowptr[i] = run;
        run += g_cnt[i];
    }
    if (t == T - 1) g_rowptr[NN] = run;
}

__global__ void k_fill(const int4* __restrict__ src4, const int4* __restrict__ dst4) {
    int i = blockIdx.x * blockDim.x + threadIdx.x;
    if (i >= NE / 8) return;
    int4 s0 = src4[2 * i], s1 = src4[2 * i + 1];
    int4 d0 = dst4[2 * i], d1 = dst4[2 * i + 1];
    int4 p0 = ((const int4*)g_epos)[2 * i];
    int4 p1 = ((const int4*)g_epos)[2 * i + 1];
    g_csrc[g_rowptr[d0.x] + p0.x] = s0.x;
    g_csrc[g_rowptr[d0.y] + p0.y] = s0.y;
    g_csrc[g_rowptr[d0.z] + p0.z] = s0.z;
    g_csrc[g_rowptr[d0.w] + p0.w] = s0.w;
    g_csrc[g_rowptr[d1.x] + p1.x] = s1.x;
    g_csrc[g_rowptr[d1.y] + p1.y] = s1.y;
    g_csrc[g_rowptr[d1.z] + p1.z] = s1.z;
    g_csrc[g_rowptr[d1.w] + p1.w] = s1.w;
}

// ================= fused softmax + aggregate (R7/R12 form) ====
template <int LAYER>
__global__ void k_gat_agg(const float* __restrict__ bias, int nodeOff, int nodeEnd) {
    __shared__ float exsAll[8][128];
    int wIn = threadIdx.x >> 5;
    int n = nodeOff + (blockIdx.x << 3) + wIn;
    if (n >= nodeEnd) return;
    float* exsw = exsAll[wIn];
    int lane = threadIdx.x & 31;
    int myh = lane >> 3;
    int beg = g_rowptr[n], end = g_rowptr[n + 1];
    float4 er4 = *(const float4*)(g_er + n * NH);

    float ax = 0.f, ay = 0.f, az = 0.f, aw = 0.f;
    float se0 = 0.f, se1 = 0.f, se2 = 0.f, se3 = 0.f;
    const __half* WhBase = g_Whh + (size_t)(lane * 4);

    for (int base = beg; base < end; base += 32) {
        int cnt = end - base; if (cnt > 32) cnt = 32;
        int sv = 0;
        float4 elv = make_float4(0.f, 0.f, 0.f, 0.f);
        if (lane < cnt) {
            sv = g_csrc[base + lane];
            elv = *(const float4*)(g_el + sv * NH);
        }
        float e0 = __expf(lrelu(elv.x + er4.x));
        float e1 = __expf(lrelu(elv.y + er4.y));
        float e2 = __expf(lrelu(elv.z + er4.z));
        float e3 = __expf(lrelu(elv.w + er4.w));
        if (lane >= cnt) { e0 = e1 = e2 = e3 = 0.f; }
        se0 += e0; se1 += e1; se2 += e2; se3 += e3;
        __syncwarp();
        *(float4*)&exsw[lane * 4] = make_float4(e0, e1, e2, e3);
        __syncwarp();
#pragma unroll 8
        for (int j = 0; j < cnt; j++) {
            int s = __shfl_sync(0xFFFFFFFFu, sv, j);
            float exh = exsw[j * 4 + myh];
            uint2 u = *(const uint2*)(WhBase + (size_t)s * DHID);
            float2 f0 = __half22float2(*(__half2*)&u.x);
            float2 f1 = __half22float2(*(__half2*)&u.y);
            ax = fmaf(exh, f0.x, ax);
            ay = fmaf(exh, f0.y, ay);
            az = fmaf(exh, f1.x, az);
            aw = fmaf(exh, f1.y, aw);
        }
    }
#pragma unroll
    for (int o = 16; o > 0; o >>= 1) {
        se0 += __shfl_xor_sync(0xFFFFFFFFu, se0, o);
        se1 += __shfl_xor_sync(0xFFFFFFFFu, se1, o);
        se2 += __shfl_xor_sync(0xFFFFFFFFu, se2, o);
        se3 += __shfl_xor_sync(0xFFFFFFFFu, se3, o);
    }
    float seh = myh < 2 ? (myh == 0 ? se0 : se1) : (myh == 2 ? se2 : se3);
    float r = 1.0f / (seh + EPSV);
    ax *= r; ay *= r; az *= r; aw *= r;

    if (LAYER == 1) {
        int d = lane * 4;
        float4 v;
        v.x = ax + bias[d + 0];
        v.y = ay + bias[d + 1];
        v.z = az + bias[d + 2];
        v.w = aw + bias[d + 3];
        v.x = v.x > 0.f ? v.x : (__expf(v.x) - 1.0f);
        v.y = v.y > 0.f ? v.y : (__expf(v.y) - 1.0f);
        v.z = v.z > 0.f ? v.z : (__expf(v.z) - 1.0f);
        v.w = v.w > 0.f ? v.w : (__expf(v.w) - 1.0f);
        v.x = round_tf32(v.x); v.y = round_tf32(v.y);
        v.z = round_tf32(v.z); v.w = round_tf32(v.w);
        *(float4*)(g_z + (size_t)n * DHID + d) = v;
    } else {
        int d = lane * 4;
        ax += bias[d + 0]; ay += bias[d + 1]; az += bias[d + 2]; aw += bias[d + 3];
#pragma unroll
        for (int o = 8; o <= 16; o <<= 1) {
            ax += __shfl_xor_sync(0xFFFFFFFFu, ax, o);
            ay += __shfl_xor_sync(0xFFFFFFFFu, ay, o);
            az += __shfl_xor_sync(0xFFFFFFFFu, az, o);
            aw += __shfl_xor_sync(0xFFFFFFFFu, aw, o);
        }
        if (lane < 8) {
            float4 v = make_float4(round_tf32(0.25f * ax), round_tf32(0.25f * ay),
                                   round_tf32(0.25f * az), round_tf32(0.25f * aw));
            *(float4*)(g_z2 + (size_t)n * DHEAD + lane * 4) = v;
        }
    }
}

// ================= launch =================
extern "C" void kernel_launch(void* const* d_in, const int* in_sizes, int n_in,
                              void* d_out, int out_size) {
    const float* h   = (const float*)d_in[0];
    const int*   src = (const int*)d_in[1];
    const int*   dst = (const int*)d_in[2];
    const float* W1  = (const float*)d_in[3];
    const float* al1 = (const float*)d_in[4];
    const float* ar1 = (const float*)d_in[5];
    const float* b1  = (const float*)d_in[6];
    const float* W2  = (const float*)d_in[7];
    const float* al2 = (const float*)d_in[8];
    const float* ar2 = (const float*)d_in[9];
    const float* b2  = (const float*)d_in[10];
    const float* Wp  = (const float*)d_in[11];
    const float* bp  = (const float*)d_in[12];
    float* out = (float*)d_out;

    float *p_z, *p_z2, *p_W1t, *p_W2t, *p_Wpt;
    int *p_cnt;
    cudaGetSymbolAddress((void**)&p_z,   g_z);
    cudaGetSymbolAddress((void**)&p_z2,  g_z2);
    cudaGetSymbolAddress((void**)&p_cnt, g_cnt);
    cudaGetSymbolAddress((void**)&p_W1t, g_W1t);
    cudaGetSymbolAddress((void**)&p_W2t, g_W2t);
    cudaGetSymbolAddress((void**)&p_Wpt, g_Wpt);

    const int TPB = 256;
    int gEdge8 = (NE / 8 + TPB - 1) / TPB;    // 391

    dim3 gemmGrid1(1, (NN + 63) / 64);                    // full layer GEMMs
    dim3 gemmGridPa(OUTD / 128, SPLIT / 64);              // proj rows [0, SPLIT)
    dim3 gemmGridPb(OUTD / 128, (NN - SPLIT + 63) / 64);  // proj rows [SPLIT, NN)

    int aggFull = (NN + 7) / 8;
    int aggA = SPLIT / 8;                 // 3128
    int aggB = (NN - SPLIT + 7) / 8;      // 3122

    // ---- fork ----
    cudaEventRecord(g_evFork, 0);
    cudaStreamWaitEvent(g_s2, g_evFork, 0);
    cudaStreamWaitEvent(g_s3, g_evFork, 0);

    // s3: weight rounding
    k_round_w1<<<64, 256, 0, g_s3>>>(W1);
    cudaEventRecord(g_evW1, g_s3);
    k_round_w2p<<<128, 256, 0, g_s3>>>(W2, Wp);
    cudaEventRecord(g_evW2p, g_s3);

    // s2: CSR build
    cudaMemsetAsync(p_cnt, 0, NN * sizeof(int), g_s2);
    k_count<<<gEdge8, TPB, 0, g_s2>>>((const int4*)dst);
    k_scan<<<1, 1024, 0, g_s2>>>();
    k_fill<<<gEdge8, TPB, 0, g_s2>>>((const int4*)src, (const int4*)dst);
    cudaEventRecord(g_evCsr, g_s2);

    // ===== layer 1 =====
    cudaStreamWaitEvent(0, g_evW1, 0);
    gemm_tc<1, 1><<<gemmGrid1, 256, SMEM_BYTES>>>(h, p_W1t, nullptr, nullptr,
                                                  NN, DHID, DHID, al1, ar1, 0);
    cudaStreamWaitEvent(0, g_evCsr, 0);
    k_gat_agg<1><<<aggFull, 256>>>(b1, 0, NN);

    // ===== layer 2 =====
    cudaStreamWaitEvent(0, g_evW2p, 0);
    gemm_tc<1, 0><<<gemmGrid1, 256, SMEM_BYTES>>>(p_z, p_W2t, nullptr, nullptr,
                                                  NN, DHID, DHID, al2, ar2, 0);
    k_gat_agg<2><<<aggA, 256>>>(b2, 0, SPLIT);
    cudaEventRecord(g_evA2a, 0);
    k_gat_agg<2><<<aggB, 256>>>(b2, SPLIT, NN);

    // ===== projection: half 1 on s2 (overlaps agg2 half 2), half 2 on main ====
    cudaStreamWaitEvent(g_s2, g_evA2a, 0);
    cudaStreamWaitEvent(g_s2, g_evW2p, 0);
    gemm_tc<0, 0><<<gemmGridPa, 256, SMEM_BYTES, g_s2>>>(p_z2, p_Wpt, bp, out,
                                                         SPLIT, OUTD, DHEAD,
                                                         nullptr, nullptr, 0);
    cudaEventRecord(g_evP1, g_s2);

    gemm_tc<0, 0><<<gemmGridPb, 256, SMEM_BYTES>>>(p_z2, p_Wpt, bp, out,
                                                   NN, OUTD, DHEAD,
                                                   nullptr, nullptr, SPLIT);
    cudaStreamWaitEvent(0, g_evP1, 0);
}

// round 14
// speedup vs baseline: 1.2450x; 1.2450x over previous
#include <cuda_runtime.h>
#include <cuda_fp16.h>
#include <math.h>
#include <stdint.h>

#define NN 50000
#define NE 800000
#define DHID 128
#define NH 4
#define DHEAD 32
#define OUTD 512
#define NEG_SLOPE 0.2f
#define EPSV 1e-9f

// GEMM smem layout (floats): 3 stages A[64][20] + 3 stages B[16][132]
#define A_STRIDE 20
#define B_STRIDE 132
#define A_STAGE (64 * A_STRIDE)
#define B_STAGE (16 * B_STRIDE)
#define SMEM_FLOATS (3 * A_STAGE + 3 * B_STAGE)
#define SMEM_BYTES (SMEM_FLOATS * 4)      // 40704

// parallel scan config: 25 blocks x 256 threads x 8 nodes = 51200 >= NN
#define SCAN_BLOCKS 25
#define SCAN_T 256
#define SCAN_CH 8

// ---------------- scratch (device globals; no allocation) ----------------
__device__ __half g_Whh[NN * DHID];
__device__ float g_z[NN * DHID];      // tf32-rounded
__device__ float g_el[NN * NH];
__device__ float g_er[NN * NH];
__device__ float g_z2[NN * DHEAD];    // tf32-rounded
__device__ int   g_cnt[NN];
__device__ int   g_rowptr[NN + 1];
__device__ int   g_epos[NE];
__device__ int   g_csrc[NE];
__device__ float g_W1t[DHID * DHID];
__device__ float g_W2t[DHID * DHID];
__device__ float g_Wpt[DHEAD * OUTD];
__device__ int   g_bsum[SCAN_BLOCKS];
__device__ int   g_boff[SCAN_BLOCKS];

__device__ __forceinline__ float lrelu(float x) {
    return x > 0.0f ? x : NEG_SLOPE * x;
}

__device__ __forceinline__ uint32_t f2tf32(float x) {
    uint32_t u;
    asm("cvt.rna.tf32.f32 %0, %1;" : "=r"(u) : "f"(x));
    return u;
}

__device__ __forceinline__ float round_tf32(float x) {
    return __uint_as_float(f2tf32(x));
}

__device__ __forceinline__ void mma_tf32(float* c, const uint32_t* a, const uint32_t* b) {
    asm volatile(
        "mma.sync.aligned.m16n8k8.row.col.f32.tf32.tf32.f32 "
        "{%0,%1,%2,%3}, {%4,%5,%6,%7}, {%8,%9}, {%0,%1,%2,%3};"
        : "+f"(c[0]), "+f"(c[1]), "+f"(c[2]), "+f"(c[3])
        : "r"(a[0]), "r"(a[1]), "r"(a[2]), "r"(a[3]), "r"(b[0]), "r"(b[1]));
}

__device__ __forceinline__ uint32_t su(const void* p) {
    return (uint32_t)__cvta_generic_to_shared(p);
}

__device__ __forceinline__ void cp16(uint32_t dst, const void* src, bool p) {
    int sz = p ? 16 : 0;
    asm volatile("cp.async.cg.shared.global [%0], [%1], 16, %2;"
                 :: "r"(dst), "l"(src), "r"(sz));
}

// ============ weight pre-rounding ====
__global__ void k_round_weights(const float* __restrict__ W1,
                                const float* __restrict__ W2,
                                const float* __restrict__ Wp) {
    int i = blockIdx.x * blockDim.x + threadIdx.x;   // 0..49151
    if (i < 16384) {
        g_W1t[i] = round_tf32(W1[i]);
    } else if (i < 32768) {
        g_W2t[i - 16384] = round_tf32(W2[i - 16384]);
    } else if (i < 49152) {
        g_Wpt[i - 32768] = round_tf32(Wp[i - 32768]);
    }
}

// ================= tensor-core GEMM (tf32 mma.sync) =================
// Block tile 64x128, 8 warps (2m x 4n), 3-stage cp.async.
// CVTA: cvt A fragments at load (else A pre-rounded). B always pre-rounded.
// FUSE=1: writes fp16 g_Whh + g_el/g_er (grid.x==1, N==128); no fp32 C.
// FUSE=0: writes fp32 C (+bias).
template <int FUSE, int CVTA>
__global__ void __launch_bounds__(256, 3)
gemm_tc(const float* __restrict__ A, const float* __restrict__ B,
        const float* __restrict__ bias, float* __restrict__ C,
        int M, int N, int K,
        const float* __restrict__ al, const float* __restrict__ ar) {
    extern __shared__ float smem[];

    const int tid = threadIdx.x;
    const int wid = tid >> 5, lane = tid & 31;
    const int g = lane >> 2, t = lane & 3;
    const int wm = wid & 1;
    const int wn = wid >> 1;
    const int rowBase = blockIdx.y * 64;
    const int colBase = blockIdx.x * 128;

    const int aRow = tid >> 2, aK0 = (tid & 3) * 4;
    const int bK0 = tid >> 5, bN0 = (tid & 31) * 4;
    const bool ap = (rowBase + aRow) < M;
    const float* aSrc = A + (size_t)(ap ? rowBase + aRow : 0) * K + aK0;
    const float* bSrc0 = B + (size_t)bK0 * N + colBase + bN0;
    const float* bSrc1 = B + (size_t)(bK0 + 8) * N + colBase + bN0;

    float acc[2][4][4];
#pragma unroll
    for (int mf = 0; mf < 2; mf++)
#pragma unroll
        for (int nf = 0; nf < 4; nf++)
#pragma unroll
            for (int r = 0; r < 4; r++) acc[mf][nf][r] = 0.0f;

    const int nStages = K >> 4;

    uint32_t aDst = su(smem + aRow * A_STRIDE + aK0);
    uint32_t bDst0 = su(smem + 3 * A_STAGE + bK0 * B_STRIDE + bN0);
    uint32_t bDst1 = su(smem + 3 * A_STAGE + (bK0 + 8) * B_STRIDE + bN0);

#pragma unroll
    for (int s = 0; s < 2; s++) {
        int k0g = s * 16;
        cp16(aDst + s * A_STAGE * 4, aSrc + k0g, ap);
        cp16(bDst0 + s * B_STAGE * 4, bSrc0 + (size_t)k0g * N, true);
        cp16(bDst1 + s * B_STAGE * 4, bSrc1 + (size_t)k0g * N, true);
        asm volatile("cp.async.commit_group;");
    }

    for (int st = 0; st < nStages; st++) {
        if (nStages - st >= 2) asm volatile("cp.async.wait_group 1;" ::: "memory");
        else                   asm volatile("cp.async.wait_group 0;" ::: "memory");
        __syncthreads();

        const int cur = st % 3;
        const float* Asf = smem + cur * A_STAGE;
        const float* Bsf = smem + 3 * A_STAGE + cur * B_STAGE;

#pragma unroll
        for (int kk = 0; kk < 2; kk++) {
            const int k0 = kk * 8;
            uint32_t af[2][4], bf[4][2];
#pragma unroll
            for (int mf = 0; mf < 2; mf++) {
                int r0 = wm * 32 + mf * 16 + g;
                float a0 = Asf[r0 * A_STRIDE + k0 + t];
                float a1 = Asf[(r0 + 8) * A_STRIDE + k0 + t];
                float a2 = Asf[r0 * A_STRIDE + k0 + t + 4];
                float a3 = Asf[(r0 + 8) * A_STRIDE + k0 + t + 4];
                if (CVTA) {
                    af[mf][0] = f2tf32(a0); af[mf][1] = f2tf32(a1);
                    af[mf][2] = f2tf32(a2); af[mf][3] = f2tf32(a3);
                } else {
                    af[mf][0] = __float_as_uint(a0); af[mf][1] = __float_as_uint(a1);
                    af[mf][2] = __float_as_uint(a2); af[mf][3] = __float_as_uint(a3);
                }
            }
#pragma unroll
            for (int nf = 0; nf < 4; nf++) {
                int n0 = wn * 32 + nf * 8 + g;
                bf[nf][0] = __float_as_uint(Bsf[(k0 + t) * B_STRIDE + n0]);
                bf[nf][1] = __float_as_uint(Bsf[(k0 + t + 4) * B_STRIDE + n0]);
            }
#pragma unroll
            for (int mf = 0; mf < 2; mf++)
#pragma unroll
                for (int nf = 0; nf < 4; nf++)
                    mma_tf32(acc[mf][nf], af[mf], bf[nf]);
        }

        if (st + 2 < nStages) {
            int s = (st + 2) % 3;
            int k0g = (st + 2) * 16;
            cp16(aDst + s * A_STAGE * 4, aSrc + k0g, ap);
            cp16(bDst0 + s * B_STAGE * 4, bSrc0 + (size_t)k0g * N, true);
            cp16(bDst1 + s * B_STAGE * 4, bSrc1 + (size_t)k0g * N, true);
            asm volatile("cp.async.commit_group;");
        }
    }

    if (!FUSE) {
#pragma unroll
        for (int mf = 0; mf < 2; mf++) {
            int row0 = rowBase + wm * 32 + mf * 16 + g;
#pragma unroll
            for (int nf = 0; nf < 4; nf++) {
                int col = colBase + wn * 32 + nf * 8 + 2 * t;
                float b0 = bias ? bias[col] : 0.f;
                float b1 = bias ? bias[col + 1] : 0.f;
                if (row0 < M) {
                    float2 v = make_float2(acc[mf][nf][0] + b0, acc[mf][nf][1] + b1);
                    *(float2*)(C + (size_t)row0 * N + col) = v;
                }
                if (row0 + 8 < M) {
                    float2 v = make_float2(acc[mf][nf][2] + b0, acc[mf][nf][3] + b1);
                    *(float2*)(C + (size_t)(row0 + 8) * N + col) = v;
                }
            }
        }
    } else {
        float elp[2][2] = {}, erp[2][2] = {};
#pragma unroll
        for (int nf = 0; nf < 4; nf++) {
            int col = wn * 32 + nf * 8 + 2 * t;
            float la0 = al[col], la1 = al[col + 1];
            float ra0 = ar[col], ra1 = ar[col + 1];
#pragma unroll
            for (int mf = 0; mf < 2; mf++) {
                elp[mf][0] += acc[mf][nf][0] * la0 + acc[mf][nf][1] * la1;
                elp[mf][1] += acc[mf][nf][2] * la0 + acc[mf][nf][3] * la1;
                erp[mf][0] += acc[mf][nf][0] * ra0 + acc[mf][nf][1] * ra1;
                erp[mf][1] += acc[mf][nf][2] * ra0 + acc[mf][nf][3] * ra1;
                int row0 = rowBase + wm * 32 + mf * 16 + g;
                if (row0 < M) {
                    __half2 hv = __floats2half2_rn(acc[mf][nf][0], acc[mf][nf][1]);
                    *(__half2*)(g_Whh + (size_t)row0 * DHID + col) = hv;
                }
                if (row0 + 8 < M) {
                    __half2 hv = __floats2half2_rn(acc[mf][nf][2], acc[mf][nf][3]);
                    *(__half2*)(g_Whh + (size_t)(row0 + 8) * DHID + col) = hv;
                }
            }
        }
#pragma unroll
        for (int mf = 0; mf < 2; mf++)
#pragma unroll
            for (int rh = 0; rh < 2; rh++) {
                float v = elp[mf][rh];
                v += __shfl_xor_sync(0xFFFFFFFFu, v, 1);
                v += __shfl_xor_sync(0xFFFFFFFFu, v, 2);
                elp[mf][rh] = v;
                float w = erp[mf][rh];
                w += __shfl_xor_sync(0xFFFFFFFFu, w, 1);
                w += __shfl_xor_sync(0xFFFFFFFFu, w, 2);
                erp[mf][rh] = w;
            }
        if (t == 0) {
#pragma unroll
            for (int mf = 0; mf < 2; mf++)
#pragma unroll
                for (int rh = 0; rh < 2; rh++) {
                    int gr = rowBase + wm * 32 + mf * 16 + g + rh * 8;
                    if (gr < M) {
                        g_el[gr * NH + wn] = elp[mf][rh];
                        g_er[gr * NH + wn] = erp[mf][rh];
                    }
                }
        }
    }
}

// ---------------- streams/events + func attrs ----------------
static cudaStream_t g_s2;
static cudaEvent_t g_evFork, g_evCsr;
struct HostInit {
    HostInit() {
        cudaStreamCreateWithFlags(&g_s2, cudaStreamNonBlocking);
        cudaEventCreateWithFlags(&g_evFork, cudaEventDisableTiming);
        cudaEventCreateWithFlags(&g_evCsr, cudaEventDisableTiming);
        cudaFuncSetAttribute((const void*)gemm_tc<0, 0>, cudaFuncAttributeMaxDynamicSharedMemorySize, SMEM_BYTES);
        cudaFuncSetAttribute((const void*)gemm_tc<1, 0>, cudaFuncAttributeMaxDynamicSharedMemorySize, SMEM_BYTES);
        cudaFuncSetAttribute((const void*)gemm_tc<1, 1>, cudaFuncAttributeMaxDynamicSharedMemorySize, SMEM_BYTES);
    }
};
static HostInit g_hostInit;

// ================= CSR build (int4-vectorized, epos-based; R12 form) =========
__global__ void k_count(const int4* __restrict__ dst4) {
    int i = blockIdx.x * blockDim.x + threadIdx.x;
    if (i >= NE / 4) return;
    int4 d = dst4[i];
    int4 p;
    p.x = atomicAdd(&g_cnt[d.x], 1);
    p.y = atomicAdd(&g_cnt[d.y], 1);
    p.z = atomicAdd(&g_cnt[d.z], 1);
    p.w = atomicAdd(&g_cnt[d.w], 1);
    ((int4*)g_epos)[i] = p;
}

// ---- 3-phase parallel exclusive scan over g_cnt -> g_rowptr ----
__global__ void k_scan1() {
    __shared__ int wsum[SCAN_T / 32];
    int t = blockIdx.x * SCAN_T + threadIdx.x;
    int lo = t * SCAN_CH;
    int hi = lo + SCAN_CH; if (hi > NN) hi = NN;
    int s = 0;
    for (int i = lo; i < hi && lo < NN; i++) s += g_cnt[i];
    int lane = threadIdx.x & 31, w = threadIdx.x >> 5;
#pragma unroll
    for (int o = 16; o > 0; o >>= 1) s += __shfl_down_sync(0xFFFFFFFFu, s, o);
    if (lane == 0) wsum[w] = s;
    __syncthreads();
    if (threadIdx.x == 0) {
        int tot = 0;
#pragma unroll
        for (int i = 0; i < SCAN_T / 32; i++) tot += wsum[i];
        g_bsum[blockIdx.x] = tot;
    }
}

__global__ void k_scan2() {
    int t = threadIdx.x;          // 32 threads
    int v = (t < SCAN_BLOCKS) ? g_bsum[t] : 0;
    int incl = v;
#pragma unroll
    for (int o = 1; o < 32; o <<= 1) {
        int u = __shfl_up_sync(0xFFFFFFFFu, incl, o);
        if (t >= o) incl += u;
    }
    if (t < SCAN_BLOCKS) g_boff[t] = incl - v;
    if (t == 31) g_rowptr[NN] = incl;   // total (lanes >= SCAN_BLOCKS add 0)
}

__global__ void k_scan3() {
    __shared__ int wpref[SCAN_T / 32];
    int tIn = threadIdx.x;
    int t = blockIdx.x * SCAN_T + tIn;
    int lo = t * SCAN_CH;
    int hi = lo + SCAN_CH; if (hi > NN) hi = NN;
    int c[SCAN_CH];
    int s = 0;
    int cntv = (lo < NN) ? (hi - lo) : 0;
    for (int i = 0; i < cntv; i++) { c[i] = g_cnt[lo + i]; s += c[i]; }
    int lane = tIn & 31, w = tIn >> 5;
    int incl = s;
#pragma unroll
    for (int o = 1; o < 32; o <<= 1) {
        int u = __shfl_up_sync(0xFFFFFFFFu, incl, o);
        if (lane >= o) incl += u;
    }
    if (lane == 31) wpref[w] = incl;
    __syncthreads();
    int woff = 0;
    for (int i = 0; i < w; i++) woff += wpref[i];
    int run = g_boff[blockIdx.x] + woff + incl - s;
    for (int i = 0; i < cntv; i++) {
        g_rowptr[lo + i] = run;
        run += c[i];
    }
}

__global__ void k_fill(const int4* __restrict__ src4, const int4* __restrict__ dst4) {
    int i = blockIdx.x * blockDim.x + threadIdx.x;
    if (i >= NE / 4) return;
    int4 s = src4[i];
    int4 d = dst4[i];
    int4 p = ((const int4*)g_epos)[i];
    g_csrc[g_rowptr[d.x] + p.x] = s.x;
    g_csrc[g_rowptr[d.y] + p.y] = s.y;
    g_csrc[g_rowptr[d.z] + p.z] = s.z;
    g_csrc[g_rowptr[d.w] + p.w] = s.w;
}

// ================= fused softmax + aggregate (R7/R12 form) ====
template <int LAYER>
__global__ void k_gat_agg(const float* __restrict__ bias) {
    __shared__ float exsAll[8][128];
    int wIn = threadIdx.x >> 5;
    int n = (blockIdx.x << 3) + wIn;
    if (n >= NN) return;
    float* exsw = exsAll[wIn];
    int lane = threadIdx.x & 31;
    int myh = lane >> 3;
    int beg = g_rowptr[n], end = g_rowptr[n + 1];
    float4 er4 = *(const float4*)(g_er + n * NH);

    float ax = 0.f, ay = 0.f, az = 0.f, aw = 0.f;
    float se0 = 0.f, se1 = 0.f, se2 = 0.f, se3 = 0.f;
    const __half* WhBase = g_Whh + (size_t)(lane * 4);

    for (int base = beg; base < end; base += 32) {
        int cnt = end - base; if (cnt > 32) cnt = 32;
        int sv = 0;
        float4 elv = make_float4(0.f, 0.f, 0.f, 0.f);
        if (lane < cnt) {
            sv = g_csrc[base + lane];
            elv = *(const float4*)(g_el + sv * NH);
        }
        float e0 = __expf(lrelu(elv.x + er4.x));
        float e1 = __expf(lrelu(elv.y + er4.y));
        float e2 = __expf(lrelu(elv.z + er4.z));
        float e3 = __expf(lrelu(elv.w + er4.w));
        if (lane >= cnt) { e0 = e1 = e2 = e3 = 0.f; }
        se0 += e0; se1 += e1; se2 += e2; se3 += e3;
        __syncwarp();
        *(float4*)&exsw[lane * 4] = make_float4(e0, e1, e2, e3);
        __syncwarp();
#pragma unroll 8
        for (int j = 0; j < cnt; j++) {
            int s = __shfl_sync(0xFFFFFFFFu, sv, j);
            float exh = exsw[j * 4 + myh];
            uint2 u = *(const uint2*)(WhBase + (size_t)s * DHID);
            float2 f0 = __half22float2(*(__half2*)&u.x);
            float2 f1 = __half22float2(*(__half2*)&u.y);
            ax = fmaf(exh, f0.x, ax);
            ay = fmaf(exh, f0.y, ay);
            az = fmaf(exh, f1.x, az);
            aw = fmaf(exh, f1.y, aw);
        }
    }
#pragma unroll
    for (int o = 16; o > 0; o >>= 1) {
        se0 += __shfl_xor_sync(0xFFFFFFFFu, se0, o);
        se1 += __shfl_xor_sync(0xFFFFFFFFu, se1, o);
        se2 += __shfl_xor_sync(0xFFFFFFFFu, se2, o);
        se3 += __shfl_xor_sync(0xFFFFFFFFu, se3, o);
    }
    float seh = myh < 2 ? (myh == 0 ? se0 : se1) : (myh == 2 ? se2 : se3);
    float r = 1.0f / (seh + EPSV);
    ax *= r; ay *= r; az *= r; aw *= r;

    if (LAYER == 1) {
        int d = lane * 4;
        float4 v;
        v.x = ax + bias[d + 0];
        v.y = ay + bias[d + 1];
        v.z = az + bias[d + 2];
        v.w = aw + bias[d + 3];
        v.x = v.x > 0.f ? v.x : (__expf(v.x) - 1.0f);
        v.y = v.y > 0.f ? v.y : (__expf(v.y) - 1.0f);
        v.z = v.z > 0.f ? v.z : (__expf(v.z) - 1.0f);
        v.w = v.w > 0.f ? v.w : (__expf(v.w) - 1.0f);
        v.x = round_tf32(v.x); v.y = round_tf32(v.y);
        v.z = round_tf32(v.z); v.w = round_tf32(v.w);
        *(float4*)(g_z + (size_t)n * DHID + d) = v;
    } else {
        int d = lane * 4;
        ax += bias[d + 0]; ay += bias[d + 1]; az += bias[d + 2]; aw += bias[d + 3];
#pragma unroll
        for (int o = 8; o <= 16; o <<= 1) {
            ax += __shfl_xor_sync(0xFFFFFFFFu, ax, o);
            ay += __shfl_xor_sync(0xFFFFFFFFu, ay, o);
            az += __shfl_xor_sync(0xFFFFFFFFu, az, o);
            aw += __shfl_xor_sync(0xFFFFFFFFu, aw, o);
        }
        if (lane < 8) {
            float4 v = make_float4(round_tf32(0.25f * ax), round_tf32(0.25f * ay),
                                   round_tf32(0.25f * az), round_tf32(0.25f * aw));
            *(float4*)(g_z2 + (size_t)n * DHEAD + lane * 4) = v;
        }
    }
}

// ================= launch =================
extern "C" void kernel_launch(void* const* d_in, const int* in_sizes, int n_in,
                              void* d_out, int out_size) {
    const float* h   = (const float*)d_in[0];
    const int*   src = (const int*)d_in[1];
    const int*   dst = (const int*)d_in[2];
    const float* W1  = (const float*)d_in[3];
    const float* al1 = (const float*)d_in[4];
    const float* ar1 = (const float*)d_in[5];
    const float* b1  = (const float*)d_in[6];
    const float* W2  = (const float*)d_in[7];
    const float* al2 = (const float*)d_in[8];
    const float* ar2 = (const float*)d_in[9];
    const float* b2  = (const float*)d_in[10];
    const float* Wp  = (const float*)d_in[11];
    const float* bp  = (const float*)d_in[12];
    float* out = (float*)d_out;

    float *p_z, *p_z2, *p_W1t, *p_W2t, *p_Wpt;
    int *p_cnt;
    cudaGetSymbolAddress((void**)&p_z,   g_z);
    cudaGetSymbolAddress((void**)&p_z2,  g_z2);
    cudaGetSymbolAddress((void**)&p_cnt, g_cnt);
    cudaGetSymbolAddress((void**)&p_W1t, g_W1t);
    cudaGetSymbolAddress((void**)&p_W2t, g_W2t);
    cudaGetSymbolAddress((void**)&p_Wpt, g_Wpt);

    const int TPB = 256;
    int gEdge4 = (NE / 4 + TPB - 1) / TPB;
    int gAgg   = (NN + 7) / 8;

    dim3 gemmGrid1(1, (NN + 63) / 64);              // N=128
    dim3 gemmGridP(OUTD / 128, (NN + 63) / 64);     // N=512

    // ---- fork: CSR build on side stream, weights+GEMM1 on main stream ----
    cudaEventRecord(g_evFork, 0);
    cudaStreamWaitEvent(g_s2, g_evFork, 0);
    cudaMemsetAsync(p_cnt, 0, NN * sizeof(int), g_s2);
    k_count<<<gEdge4, TPB, 0, g_s2>>>((const int4*)dst);
    k_scan1<<<SCAN_BLOCKS, SCAN_T, 0, g_s2>>>();
    k_scan2<<<1, 32, 0, g_s2>>>();
    k_scan3<<<SCAN_BLOCKS, SCAN_T, 0, g_s2>>>();
    k_fill<<<gEdge4, TPB, 0, g_s2>>>((const int4*)src, (const int4*)dst);
    cudaEventRecord(g_evCsr, g_s2);

    // pre-round all weights to tf32 (49152 elements)
    k_round_weights<<<192, 256>>>(W1, W2, Wp);

    // ===== layer 1 =====  (A = h: cvt at load; B = pre-rounded W1)
    gemm_tc<1, 1><<<gemmGrid1, 256, SMEM_BYTES>>>(h, p_W1t, nullptr, nullptr,
                                                  NN, DHID, DHID, al1, ar1);
    cudaStreamWaitEvent(0, g_evCsr, 0);   // join: agg needs CSR
    k_gat_agg<1><<<gAgg, 256>>>(b1);

    // ===== layer 2 =====  (A = pre-rounded z; B = pre-rounded W2: no cvts)
    gemm_tc<1, 0><<<gemmGrid1, 256, SMEM_BYTES>>>(p_z, p_W2t, nullptr, nullptr,
                                                  NN, DHID, DHID, al2, ar2);
    k_gat_agg<2><<<gAgg, 256>>>(b2);

    // ===== projection head =====  (A = pre-rounded z2; B = pre-rounded Wp)
    gemm_tc<0, 0><<<gemmGridP, 256, SMEM_BYTES>>>(p_z2, p_Wpt, bp, out,
                                                  NN, OUTD, DHEAD, nullptr, nullptr);
}

// round 15
// speedup vs baseline: 1.2641x; 1.0154x over previous
#include <cuda_runtime.h>
#include <cuda_fp16.h>
#include <math.h>
#include <stdint.h>

#define NN 50000
#define NE 800000
#define DHID 128
#define NH 4
#define DHEAD 32
#define OUTD 512
#define NEG_SLOPE 0.2f
#define EPSV 1e-9f

// GEMM smem layout (floats): 3 stages A[64][20] + 3 stages B[16][132]
#define A_STRIDE 20
#define B_STRIDE 132
#define A_STAGE (64 * A_STRIDE)
#define B_STAGE (16 * B_STRIDE)
#define SMEM_FLOATS (3 * A_STAGE + 3 * B_STAGE)
#define SMEM_BYTES (SMEM_FLOATS * 4)      // 40704

// parallel scan config: 98 blocks x 256 threads x 2 nodes = 50176 >= NN
#define SCAN_BLOCKS 98
#define SCAN_T 256
#define SCAN_CH 2

// ---------------- scratch (device globals; no allocation) ----------------
__device__ __half g_Whh[NN * DHID];
__device__ float g_z[NN * DHID];      // tf32-rounded
__device__ float g_el[NN * NH];
__device__ float g_er[NN * NH];
__device__ float g_z2[NN * DHEAD];    // tf32-rounded
__device__ int   g_cnt[NN];           // zero at entry; re-zeroed by k_scan3
__device__ int   g_rowptr[NN + 1];
__device__ int   g_epos[NE];
__device__ int   g_csrc[NE];
__device__ float g_W1t[DHID * DHID];
__device__ float g_W2t[DHID * DHID];
__device__ float g_Wpt[DHEAD * OUTD];
__device__ int   g_bsum[SCAN_BLOCKS];
__device__ int   g_boff[SCAN_BLOCKS];

__device__ __forceinline__ float lrelu(float x) {
    return x > 0.0f ? x : NEG_SLOPE * x;
}

__device__ __forceinline__ uint32_t f2tf32(float x) {
    uint32_t u;
    asm("cvt.rna.tf32.f32 %0, %1;" : "=r"(u) : "f"(x));
    return u;
}

__device__ __forceinline__ float round_tf32(float x) {
    return __uint_as_float(f2tf32(x));
}

__device__ __forceinline__ void mma_tf32(float* c, const uint32_t* a, const uint32_t* b) {
    asm volatile(
        "mma.sync.aligned.m16n8k8.row.col.f32.tf32.tf32.f32 "
        "{%0,%1,%2,%3}, {%4,%5,%6,%7}, {%8,%9}, {%0,%1,%2,%3};"
        : "+f"(c[0]), "+f"(c[1]), "+f"(c[2]), "+f"(c[3])
        : "r"(a[0]), "r"(a[1]), "r"(a[2]), "r"(a[3]), "r"(b[0]), "r"(b[1]));
}

__device__ __forceinline__ uint32_t su(const void* p) {
    return (uint32_t)__cvta_generic_to_shared(p);
}

__device__ __forceinline__ void cp16(uint32_t dst, const void* src, bool p) {
    int sz = p ? 16 : 0;
    asm volatile("cp.async.cg.shared.global [%0], [%1], 16, %2;"
                 :: "r"(dst), "l"(src), "r"(sz));
}

// ============ weight pre-rounding ====
__global__ void k_round_weights(const float* __restrict__ W1,
                                const float* __restrict__ W2,
                                const float* __restrict__ Wp) {
    int i = blockIdx.x * blockDim.x + threadIdx.x;   // 0..49151
    if (i < 16384) {
        g_W1t[i] = round_tf32(W1[i]);
    } else if (i < 32768) {
        g_W2t[i - 16384] = round_tf32(W2[i - 16384]);
    } else if (i < 49152) {
        g_Wpt[i - 32768] = round_tf32(Wp[i - 32768]);
    }
}

// ================= tensor-core GEMM (tf32 mma.sync) =================
// Block tile 64x128, 8 warps (2m x 4n), 3-stage cp.async.
// CVTA: cvt A fragments at load (else A pre-rounded). B always pre-rounded.
// FUSE=1: writes fp16 g_Whh + g_el/g_er (grid.x==1, N==128); no fp32 C.
// FUSE=0: writes fp32 C (+bias).
template <int FUSE, int CVTA>
__global__ void __launch_bounds__(256, 3)
gemm_tc(const float* __restrict__ A, const float* __restrict__ B,
        const float* __restrict__ bias, float* __restrict__ C,
        int M, int N, int K,
        const float* __restrict__ al, const float* __restrict__ ar) {
    extern __shared__ float smem[];

    const int tid = threadIdx.x;
    const int wid = tid >> 5, lane = tid & 31;
    const int g = lane >> 2, t = lane & 3;
    const int wm = wid & 1;
    const int wn = wid >> 1;
    const int rowBase = blockIdx.y * 64;
    const int colBase = blockIdx.x * 128;

    const int aRow = tid >> 2, aK0 = (tid & 3) * 4;
    const int bK0 = tid >> 5, bN0 = (tid & 31) * 4;
    const bool ap = (rowBase + aRow) < M;
    const float* aSrc = A + (size_t)(ap ? rowBase + aRow : 0) * K + aK0;
    const float* bSrc0 = B + (size_t)bK0 * N + colBase + bN0;
    const float* bSrc1 = B + (size_t)(bK0 + 8) * N + colBase + bN0;

    float acc[2][4][4];
#pragma unroll
    for (int mf = 0; mf < 2; mf++)
#pragma unroll
        for (int nf = 0; nf < 4; nf++)
#pragma unroll
            for (int r = 0; r < 4; r++) acc[mf][nf][r] = 0.0f;

    const int nStages = K >> 4;

    uint32_t aDst = su(smem + aRow * A_STRIDE + aK0);
    uint32_t bDst0 = su(smem + 3 * A_STAGE + bK0 * B_STRIDE + bN0);
    uint32_t bDst1 = su(smem + 3 * A_STAGE + (bK0 + 8) * B_STRIDE + bN0);

#pragma unroll
    for (int s = 0; s < 2; s++) {
        int k0g = s * 16;
        cp16(aDst + s * A_STAGE * 4, aSrc + k0g, ap);
        cp16(bDst0 + s * B_STAGE * 4, bSrc0 + (size_t)k0g * N, true);
        cp16(bDst1 + s * B_STAGE * 4, bSrc1 + (size_t)k0g * N, true);
        asm volatile("cp.async.commit_group;");
    }

    for (int st = 0; st < nStages; st++) {
        if (nStages - st >= 2) asm volatile("cp.async.wait_group 1;" ::: "memory");
        else                   asm volatile("cp.async.wait_group 0;" ::: "memory");
        __syncthreads();

        const int cur = st % 3;
        const float* Asf = smem + cur * A_STAGE;
        const float* Bsf = smem + 3 * A_STAGE + cur * B_STAGE;

#pragma unroll
        for (int kk = 0; kk < 2; kk++) {
            const int k0 = kk * 8;
            uint32_t af[2][4], bf[4][2];
#pragma unroll
            for (int mf = 0; mf < 2; mf++) {
                int r0 = wm * 32 + mf * 16 + g;
                float a0 = Asf[r0 * A_STRIDE + k0 + t];
                float a1 = Asf[(r0 + 8) * A_STRIDE + k0 + t];
                float a2 = Asf[r0 * A_STRIDE + k0 + t + 4];
                float a3 = Asf[(r0 + 8) * A_STRIDE + k0 + t + 4];
                if (CVTA) {
                    af[mf][0] = f2tf32(a0); af[mf][1] = f2tf32(a1);
                    af[mf][2] = f2tf32(a2); af[mf][3] = f2tf32(a3);
                } else {
                    af[mf][0] = __float_as_uint(a0); af[mf][1] = __float_as_uint(a1);
                    af[mf][2] = __float_as_uint(a2); af[mf][3] = __float_as_uint(a3);
                }
            }
#pragma unroll
            for (int nf = 0; nf < 4; nf++) {
                int n0 = wn * 32 + nf * 8 + g;
                bf[nf][0] = __float_as_uint(Bsf[(k0 + t) * B_STRIDE + n0]);
                bf[nf][1] = __float_as_uint(Bsf[(k0 + t + 4) * B_STRIDE + n0]);
            }
#pragma unroll
            for (int mf = 0; mf < 2; mf++)
#pragma unroll
                for (int nf = 0; nf < 4; nf++)
                    mma_tf32(acc[mf][nf], af[mf], bf[nf]);
        }

        if (st + 2 < nStages) {
            int s = (st + 2) % 3;
            int k0g = (st + 2) * 16;
            cp16(aDst + s * A_STAGE * 4, aSrc + k0g, ap);
            cp16(bDst0 + s * B_STAGE * 4, bSrc0 + (size_t)k0g * N, true);
            cp16(bDst1 + s * B_STAGE * 4, bSrc1 + (size_t)k0g * N, true);
            asm volatile("cp.async.commit_group;");
        }
    }

    if (!FUSE) {
#pragma unroll
        for (int mf = 0; mf < 2; mf++) {
            int row0 = rowBase + wm * 32 + mf * 16 + g;
#pragma unroll
            for (int nf = 0; nf < 4; nf++) {
                int col = colBase + wn * 32 + nf * 8 + 2 * t;
                float b0 = bias ? bias[col] : 0.f;
                float b1 = bias ? bias[col + 1] : 0.f;
                if (row0 < M) {
                    float2 v = make_float2(acc[mf][nf][0] + b0, acc[mf][nf][1] + b1);
                    *(float2*)(C + (size_t)row0 * N + col) = v;
                }
                if (row0 + 8 < M) {
                    float2 v = make_float2(acc[mf][nf][2] + b0, acc[mf][nf][3] + b1);
                    *(float2*)(C + (size_t)(row0 + 8) * N + col) = v;
                }
            }
        }
    } else {
        float elp[2][2] = {}, erp[2][2] = {};
#pragma unroll
        for (int nf = 0; nf < 4; nf++) {
            int col = wn * 32 + nf * 8 + 2 * t;
            float la0 = al[col], la1 = al[col + 1];
            float ra0 = ar[col], ra1 = ar[col + 1];
#pragma unroll
            for (int mf = 0; mf < 2; mf++) {
                elp[mf][0] += acc[mf][nf][0] * la0 + acc[mf][nf][1] * la1;
                elp[mf][1] += acc[mf][nf][2] * la0 + acc[mf][nf][3] * la1;
                erp[mf][0] += acc[mf][nf][0] * ra0 + acc[mf][nf][1] * ra1;
                erp[mf][1] += acc[mf][nf][2] * ra0 + acc[mf][nf][3] * ra1;
                int row0 = rowBase + wm * 32 + mf * 16 + g;
                if (row0 < M) {
                    __half2 hv = __floats2half2_rn(acc[mf][nf][0], acc[mf][nf][1]);
                    *(__half2*)(g_Whh + (size_t)row0 * DHID + col) = hv;
                }
                if (row0 + 8 < M) {
                    __half2 hv = __floats2half2_rn(acc[mf][nf][2], acc[mf][nf][3]);
                    *(__half2*)(g_Whh + (size_t)(row0 + 8) * DHID + col) = hv;
                }
            }
        }
#pragma unroll
        for (int mf = 0; mf < 2; mf++)
#pragma unroll
            for (int rh = 0; rh < 2; rh++) {
                float v = elp[mf][rh];
                v += __shfl_xor_sync(0xFFFFFFFFu, v, 1);
                v += __shfl_xor_sync(0xFFFFFFFFu, v, 2);
                elp[mf][rh] = v;
                float w = erp[mf][rh];
                w += __shfl_xor_sync(0xFFFFFFFFu, w, 1);
                w += __shfl_xor_sync(0xFFFFFFFFu, w, 2);
                erp[mf][rh] = w;
            }
        if (t == 0) {
#pragma unroll
            for (int mf = 0; mf < 2; mf++)
#pragma unroll
                for (int rh = 0; rh < 2; rh++) {
                    int gr = rowBase + wm * 32 + mf * 16 + g + rh * 8;
                    if (gr < M) {
                        g_el[gr * NH + wn] = elp[mf][rh];
                        g_er[gr * NH + wn] = erp[mf][rh];
                    }
                }
        }
    }
}

// ---------------- streams/events + func attrs ----------------
static cudaStream_t g_s2;
static cudaEvent_t g_evFork, g_evCsr;
struct HostInit {
    HostInit() {
        cudaStreamCreateWithFlags(&g_s2, cudaStreamNonBlocking);
        cudaEventCreateWithFlags(&g_evFork, cudaEventDisableTiming);
        cudaEventCreateWithFlags(&g_evCsr, cudaEventDisableTiming);
        cudaFuncSetAttribute((const void*)gemm_tc<0, 0>, cudaFuncAttributeMaxDynamicSharedMemorySize, SMEM_BYTES);
        cudaFuncSetAttribute((const void*)gemm_tc<1, 0>, cudaFuncAttributeMaxDynamicSharedMemorySize, SMEM_BYTES);
        cudaFuncSetAttribute((const void*)gemm_tc<1, 1>, cudaFuncAttributeMaxDynamicSharedMemorySize, SMEM_BYTES);
    }
};
static HostInit g_hostInit;

// ================= CSR build (8 edges/thread, epos-based) =================
__global__ void k_count(const int4* __restrict__ dst4) {
    int i = blockIdx.x * blockDim.x + threadIdx.x;
    if (i >= NE / 8) return;
    int4 d0 = dst4[2 * i], d1 = dst4[2 * i + 1];
    int4 p0, p1;
    p0.x = atomicAdd(&g_cnt[d0.x], 1);
    p0.y = atomicAdd(&g_cnt[d0.y], 1);
    p0.z = atomicAdd(&g_cnt[d0.z], 1);
    p0.w = atomicAdd(&g_cnt[d0.w], 1);
    p1.x = atomicAdd(&g_cnt[d1.x], 1);
    p1.y = atomicAdd(&g_cnt[d1.y], 1);
    p1.z = atomicAdd(&g_cnt[d1.z], 1);
    p1.w = atomicAdd(&g_cnt[d1.w], 1);
    ((int4*)g_epos)[2 * i] = p0;
    ((int4*)g_epos)[2 * i + 1] = p1;
}

// ---- 3-phase parallel exclusive scan over g_cnt -> g_rowptr ----
__global__ void k_scan1() {
    __shared__ int wsum[SCAN_T / 32];
    int t = blockIdx.x * SCAN_T + threadIdx.x;
    int lo = t * SCAN_CH;
    int hi = lo + SCAN_CH; if (hi > NN) hi = NN;
    int s = 0;
    for (int i = lo; i < hi && lo < NN; i++) s += g_cnt[i];
    int lane = threadIdx.x & 31, w = threadIdx.x >> 5;
#pragma unroll
    for (int o = 16; o > 0; o >>= 1) s += __shfl_down_sync(0xFFFFFFFFu, s, o);
    if (lane == 0) wsum[w] = s;
    __syncthreads();
    if (threadIdx.x == 0) {
        int tot = 0;
#pragma unroll
        for (int i = 0; i < SCAN_T / 32; i++) tot += wsum[i];
        g_bsum[blockIdx.x] = tot;
    }
}

// 128 threads scan SCAN_BLOCKS block sums
__global__ void k_scan2() {
    __shared__ int wsum[4];
    int t = threadIdx.x;
    int lane = t & 31, w = t >> 5;
    int v = (t < SCAN_BLOCKS) ? g_bsum[t] : 0;
    int incl = v;
#pragma unroll
    for (int o = 1; o < 32; o <<= 1) {
        int u = __shfl_up_sync(0xFFFFFFFFu, incl, o);
        if (lane >= o) incl += u;
    }
    if (lane == 31) wsum[w] = incl;
    __syncthreads();
    int off = 0;
    for (int i = 0; i < w; i++) off += wsum[i];
    if (t < SCAN_BLOCKS) g_boff[t] = off + incl - v;
    if (t == SCAN_BLOCKS - 1) g_rowptr[NN] = off + incl;
}

__global__ void k_scan3() {
    __shared__ int wpref[SCAN_T / 32];
    int tIn = threadIdx.x;
    int t = blockIdx.x * SCAN_T + tIn;
    int lo = t * SCAN_CH;
    int hi = lo + SCAN_CH; if (hi > NN) hi = NN;
    int c[SCAN_CH];
    int s = 0;
    int cntv = (lo < NN) ? (hi - lo) : 0;
    for (int i = 0; i < cntv; i++) { c[i] = g_cnt[lo + i]; s += c[i]; }
    int lane = tIn & 31, w = tIn >> 5;
    int incl = s;
#pragma unroll
    for (int o = 1; o < 32; o <<= 1) {
        int u = __shfl_up_sync(0xFFFFFFFFu, incl, o);
        if (lane >= o) incl += u;
    }
    if (lane == 31) wpref[w] = incl;
    __syncthreads();
    int woff = 0;
    for (int i = 0; i < w; i++) woff += wpref[i];
    int run = g_boff[blockIdx.x] + woff + incl - s;
    for (int i = 0; i < cntv; i++) {
        g_rowptr[lo + i] = run;
        run += c[i];
        g_cnt[lo + i] = 0;          // re-zero for next graph replay
    }
}

__global__ void k_fill(const int4* __restrict__ src4, const int4* __restrict__ dst4) {
    int i = blockIdx.x * blockDim.x + threadIdx.x;
    if (i >= NE / 8) return;
    int4 s0 = src4[2 * i], s1 = src4[2 * i + 1];
    int4 d0 = dst4[2 * i], d1 = dst4[2 * i + 1];
    int4 p0 = ((const int4*)g_epos)[2 * i];
    int4 p1 = ((const int4*)g_epos)[2 * i + 1];
    g_csrc[g_rowptr[d0.x] + p0.x] = s0.x;
    g_csrc[g_rowptr[d0.y] + p0.y] = s0.y;
    g_csrc[g_rowptr[d0.z] + p0.z] = s0.z;
    g_csrc[g_rowptr[d0.w] + p0.w] = s0.w;
    g_csrc[g_rowptr[d1.x] + p1.x] = s1.x;
    g_csrc[g_rowptr[d1.y] + p1.y] = s1.y;
    g_csrc[g_rowptr[d1.z] + p1.z] = s1.z;
    g_csrc[g_rowptr[d1.w] + p1.w] = s1.w;
}

// ================= fused softmax + aggregate (R7/R12 form) ====
template <int LAYER>
__global__ void k_gat_agg(const float* __restrict__ bias) {
    __shared__ float exsAll[8][128];
    int wIn = threadIdx.x >> 5;
    int n = (blockIdx.x << 3) + wIn;
    if (n >= NN) return;
    float* exsw = exsAll[wIn];
    int lane = threadIdx.x & 31;
    int myh = lane >> 3;
    int beg = g_rowptr[n], end = g_rowptr[n + 1];
    float4 er4 = *(const float4*)(g_er + n * NH);

    float ax = 0.f, ay = 0.f, az = 0.f, aw = 0.f;
    float se0 = 0.f, se1 = 0.f, se2 = 0.f, se3 = 0.f;
    const __half* WhBase = g_Whh + (size_t)(lane * 4);

    for (int base = beg; base < end; base += 32) {
        int cnt = end - base; if (cnt > 32) cnt = 32;
        int sv = 0;
        float4 elv = make_float4(0.f, 0.f, 0.f, 0.f);
        if (lane < cnt) {
            sv = g_csrc[base + lane];
            elv = *(const float4*)(g_el + sv * NH);
        }
        float e0 = __expf(lrelu(elv.x + er4.x));
        float e1 = __expf(lrelu(elv.y + er4.y));
        float e2 = __expf(lrelu(elv.z + er4.z));
        float e3 = __expf(lrelu(elv.w + er4.w));
        if (lane >= cnt) { e0 = e1 = e2 = e3 = 0.f; }
        se0 += e0; se1 += e1; se2 += e2; se3 += e3;
        __syncwarp();
        *(float4*)&exsw[lane * 4] = make_float4(e0, e1, e2, e3);
        __syncwarp();
#pragma unroll 8
        for (int j = 0; j < cnt; j++) {
            int s = __shfl_sync(0xFFFFFFFFu, sv, j);
            float exh = exsw[j * 4 + myh];
            uint2 u = *(const uint2*)(WhBase + (size_t)s * DHID);
            float2 f0 = __half22float2(*(__half2*)&u.x);
            float2 f1 = __half22float2(*(__half2*)&u.y);
            ax = fmaf(exh, f0.x, ax);
            ay = fmaf(exh, f0.y, ay);
            az = fmaf(exh, f1.x, az);
            aw = fmaf(exh, f1.y, aw);
        }
    }
#pragma unroll
    for (int o = 16; o > 0; o >>= 1) {
        se0 += __shfl_xor_sync(0xFFFFFFFFu, se0, o);
        se1 += __shfl_xor_sync(0xFFFFFFFFu, se1, o);
        se2 += __shfl_xor_sync(0xFFFFFFFFu, se2, o);
        se3 += __shfl_xor_sync(0xFFFFFFFFu, se3, o);
    }
    float seh = myh < 2 ? (myh == 0 ? se0 : se1) : (myh == 2 ? se2 : se3);
    float r = 1.0f / (seh + EPSV);
    ax *= r; ay *= r; az *= r; aw *= r;

    if (LAYER == 1) {
        int d = lane * 4;
        float4 v;
        v.x = ax + bias[d + 0];
        v.y = ay + bias[d + 1];
        v.z = az + bias[d + 2];
        v.w = aw + bias[d + 3];
        v.x = v.x > 0.f ? v.x : (__expf(v.x) - 1.0f);
        v.y = v.y > 0.f ? v.y : (__expf(v.y) - 1.0f);
        v.z = v.z > 0.f ? v.z : (__expf(v.z) - 1.0f);
        v.w = v.w > 0.f ? v.w : (__expf(v.w) - 1.0f);
        v.x = round_tf32(v.x); v.y = round_tf32(v.y);
        v.z = round_tf32(v.z); v.w = round_tf32(v.w);
        *(float4*)(g_z + (size_t)n * DHID + d) = v;
    } else {
        int d = lane * 4;
        ax += bias[d + 0]; ay += bias[d + 1]; az += bias[d + 2]; aw += bias[d + 3];
#pragma unroll
        for (int o = 8; o <= 16; o <<= 1) {
            ax += __shfl_xor_sync(0xFFFFFFFFu, ax, o);
            ay += __shfl_xor_sync(0xFFFFFFFFu, ay, o);
            az += __shfl_xor_sync(0xFFFFFFFFu, az, o);
            aw += __shfl_xor_sync(0xFFFFFFFFu, aw, o);
        }
        if (lane < 8) {
            float4 v = make_float4(round_tf32(0.25f * ax), round_tf32(0.25f * ay),
                                   round_tf32(0.25f * az), round_tf32(0.25f * aw));
            *(float4*)(g_z2 + (size_t)n * DHEAD + lane * 4) = v;
        }
    }
}

// ================= launch =================
extern "C" void kernel_launch(void* const* d_in, const int* in_sizes, int n_in,
                              void* d_out, int out_size) {
    const float* h   = (const float*)d_in[0];
    const int*   src = (const int*)d_in[1];
    const int*   dst = (const int*)d_in[2];
    const float* W1  = (const float*)d_in[3];
    const float* al1 = (const float*)d_in[4];
    const float* ar1 = (const float*)d_in[5];
    const float* b1  = (const float*)d_in[6];
    const float* W2  = (const float*)d_in[7];
    const float* al2 = (const float*)d_in[8];
    const float* ar2 = (const float*)d_in[9];
    const float* b2  = (const float*)d_in[10];
    const float* Wp  = (const float*)d_in[11];
    const float* bp  = (const float*)d_in[12];
    float* out = (float*)d_out;

    float *p_z, *p_z2, *p_W1t, *p_W2t, *p_Wpt;
    cudaGetSymbolAddress((void**)&p_z,   g_z);
    cudaGetSymbolAddress((void**)&p_z2,  g_z2);
    cudaGetSymbolAddress((void**)&p_W1t, g_W1t);
    cudaGetSymbolAddress((void**)&p_W2t, g_W2t);
    cudaGetSymbolAddress((void**)&p_Wpt, g_Wpt);

    const int TPB = 256;
    int gEdge8 = (NE / 8 + TPB - 1) / TPB;    // 391
    int gAgg   = (NN + 7) / 8;

    dim3 gemmGrid1(1, (NN + 63) / 64);              // N=128
    dim3 gemmGridP(OUTD / 128, (NN + 63) / 64);     // N=512

    // ---- fork: CSR build on side stream, weights+GEMM1 on main stream ----
    // g_cnt is zero at entry (zero-init at load; re-zeroed by k_scan3 each pass)
    cudaEventRecord(g_evFork, 0);
    cudaStreamWaitEvent(g_s2, g_evFork, 0);
    k_count<<<gEdge8, TPB, 0, g_s2>>>((const int4*)dst);
    k_scan1<<<SCAN_BLOCKS, SCAN_T, 0, g_s2>>>();
    k_scan2<<<1, 128, 0, g_s2>>>();
    k_scan3<<<SCAN_BLOCKS, SCAN_T, 0, g_s2>>>();
    k_fill<<<gEdge8, TPB, 0, g_s2>>>((const int4*)src, (const int4*)dst);
    cudaEventRecord(g_evCsr, g_s2);

    // pre-round all weights to tf32 (49152 elements)
    k_round_weights<<<192, 256>>>(W1, W2, Wp);

    // ===== layer 1 =====  (A = h: cvt at load; B = pre-rounded W1)
    gemm_tc<1, 1><<<gemmGrid1, 256, SMEM_BYTES>>>(h, p_W1t, nullptr, nullptr,
                                                  NN, DHID, DHID, al1, ar1);
    cudaStreamWaitEvent(0, g_evCsr, 0);   // join: agg needs CSR
    k_gat_agg<1><<<gAgg, 256>>>(b1);

    // ===== layer 2 =====  (A = pre-rounded z; B = pre-rounded W2: no cvts)
    gemm_tc<1, 0><<<gemmGrid1, 256, SMEM_BYTES>>>(p_z, p_W2t, nullptr, nullptr,
                                                  NN, DHID, DHID, al2, ar2);
    k_gat_agg<2><<<gAgg, 256>>>(b2);

    // ===== projection head =====  (A = pre-rounded z2; B = pre-rounded Wp)
    gemm_tc<0, 0><<<gemmGridP, 256, SMEM_BYTES>>>(p_z2, p_Wpt, bp, out,
                                                  NN, OUTD, DHEAD, nullptr, nullptr);
}

// round 16
// speedup vs baseline: 1.2682x; 1.0032x over previous
#include <cuda_runtime.h>
#include <cuda_fp16.h>
#include <math.h>
#include <stdint.h>

#define NN 50000
#define NE 800000
#define DHID 128
#define NH 4
#define DHEAD 32
#define OUTD 512
#define NEG_SLOPE 0.2f
#define EPSV 1e-9f

// GEMM smem layout (floats): 3 stages A[64][20] + 3 stages B[16][132]
#define A_STRIDE 20
#define B_STRIDE 132
#define A_STAGE (64 * A_STRIDE)
#define B_STAGE (16 * B_STRIDE)
#define SMEM_FLOATS (3 * A_STAGE + 3 * B_STAGE)
#define SMEM_BYTES (SMEM_FLOATS * 4)      // 40704

// parallel scan config: 98 blocks x 256 threads x 2 nodes = 50176 >= NN
#define SCAN_BLOCKS 98
#define SCAN_T 256
#define SCAN_CH 2

// ---------------- scratch (device globals; no allocation) ----------------
__device__ __half g_Whh[NN * DHID];
__device__ float g_z[NN * DHID];      // tf32-rounded
__device__ float g_el[NN * NH];
__device__ float g_er[NN * NH];
__device__ float g_z2[NN * DHEAD];    // tf32-rounded
__device__ int   g_cnt[NN];           // zero at entry; re-zeroed by k_scan3
__device__ int   g_rowptr[NN + 1];
__device__ int   g_epos[NE];
__device__ int   g_csrc[NE];
__device__ float g_W1t[DHID * DHID];
__device__ float g_W2t[DHID * DHID];
__device__ float g_Wpt[DHEAD * OUTD];
__device__ int   g_bsum[SCAN_BLOCKS];

__device__ __forceinline__ float lrelu(float x) {
    return x > 0.0f ? x : NEG_SLOPE * x;
}

__device__ __forceinline__ uint32_t f2tf32(float x) {
    uint32_t u;
    asm("cvt.rna.tf32.f32 %0, %1;" : "=r"(u) : "f"(x));
    return u;
}

__device__ __forceinline__ float round_tf32(float x) {
    return __uint_as_float(f2tf32(x));
}

__device__ __forceinline__ void mma_tf32(float* c, const uint32_t* a, const uint32_t* b) {
    asm volatile(
        "mma.sync.aligned.m16n8k8.row.col.f32.tf32.tf32.f32 "
        "{%0,%1,%2,%3}, {%4,%5,%6,%7}, {%8,%9}, {%0,%1,%2,%3};"
        : "+f"(c[0]), "+f"(c[1]), "+f"(c[2]), "+f"(c[3])
        : "r"(a[0]), "r"(a[1]), "r"(a[2]), "r"(a[3]), "r"(b[0]), "r"(b[1]));
}

__device__ __forceinline__ uint32_t su(const void* p) {
    return (uint32_t)__cvta_generic_to_shared(p);
}

__device__ __forceinline__ void cp16(uint32_t dst, const void* src, bool p) {
    int sz = p ? 16 : 0;
    asm volatile("cp.async.cg.shared.global [%0], [%1], 16, %2;"
                 :: "r"(dst), "l"(src), "r"(sz));
}

// ============ weight pre-rounding (split: W1 critical, W2/Wp deferred) ====
__global__ void k_round_w1(const float* __restrict__ W1) {
    int i = blockIdx.x * blockDim.x + threadIdx.x;   // 0..16383
    if (i < DHID * DHID) g_W1t[i] = round_tf32(W1[i]);
}
__global__ void k_round_w2p(const float* __restrict__ W2, const float* __restrict__ Wp) {
    int i = blockIdx.x * blockDim.x + threadIdx.x;   // 0..32767
    if (i < 16384) g_W2t[i] = round_tf32(W2[i]);
    else if (i < 32768) g_Wpt[i - 16384] = round_tf32(Wp[i - 16384]);
}

// ================= tensor-core GEMM (tf32 mma.sync) =================
// Block tile 64x128, 8 warps (2m x 4n), 3-stage cp.async.
// CVTA: cvt A fragments at load (else A pre-rounded). B always pre-rounded.
// FUSE=1: writes fp16 g_Whh + g_el/g_er (grid.x==1, N==128); no fp32 C.
// FUSE=0: writes fp32 C (+bias).
template <int FUSE, int CVTA>
__global__ void __launch_bounds__(256, 3)
gemm_tc(const float* __restrict__ A, const float* __restrict__ B,
        const float* __restrict__ bias, float* __restrict__ C,
        int M, int N, int K,
        const float* __restrict__ al, const float* __restrict__ ar) {
    extern __shared__ float smem[];

    const int tid = threadIdx.x;
    const int wid = tid >> 5, lane = tid & 31;
    const int g = lane >> 2, t = lane & 3;
    const int wm = wid & 1;
    const int wn = wid >> 1;
    const int rowBase = blockIdx.y * 64;
    const int colBase = blockIdx.x * 128;

    const int aRow = tid >> 2, aK0 = (tid & 3) * 4;
    const int bK0 = tid >> 5, bN0 = (tid & 31) * 4;
    const bool ap = (rowBase + aRow) < M;
    const float* aSrc = A + (size_t)(ap ? rowBase + aRow : 0) * K + aK0;
    const float* bSrc0 = B + (size_t)bK0 * N + colBase + bN0;
    const float* bSrc1 = B + (size_t)(bK0 + 8) * N + colBase + bN0;

    float acc[2][4][4];
#pragma unroll
    for (int mf = 0; mf < 2; mf++)
#pragma unroll
        for (int nf = 0; nf < 4; nf++)
#pragma unroll
            for (int r = 0; r < 4; r++) acc[mf][nf][r] = 0.0f;

    const int nStages = K >> 4;

    uint32_t aDst = su(smem + aRow * A_STRIDE + aK0);
    uint32_t bDst0 = su(smem + 3 * A_STAGE + bK0 * B_STRIDE + bN0);
    uint32_t bDst1 = su(smem + 3 * A_STAGE + (bK0 + 8) * B_STRIDE + bN0);

#pragma unroll
    for (int s = 0; s < 2; s++) {
        int k0g = s * 16;
        cp16(aDst + s * A_STAGE * 4, aSrc + k0g, ap);
        cp16(bDst0 + s * B_STAGE * 4, bSrc0 + (size_t)k0g * N, true);
        cp16(bDst1 + s * B_STAGE * 4, bSrc1 + (size_t)k0g * N, true);
        asm volatile("cp.async.commit_group;");
    }

    for (int st = 0; st < nStages; st++) {
        if (nStages - st >= 2) asm volatile("cp.async.wait_group 1;" ::: "memory");
        else                   asm volatile("cp.async.wait_group 0;" ::: "memory");
        __syncthreads();

        const int cur = st % 3;
        const float* Asf = smem + cur * A_STAGE;
        const float* Bsf = smem + 3 * A_STAGE + cur * B_STAGE;

#pragma unroll
        for (int kk = 0; kk < 2; kk++) {
            const int k0 = kk * 8;
            uint32_t af[2][4], bf[4][2];
#pragma unroll
            for (int mf = 0; mf < 2; mf++) {
                int r0 = wm * 32 + mf * 16 + g;
                float a0 = Asf[r0 * A_STRIDE + k0 + t];
                float a1 = Asf[(r0 + 8) * A_STRIDE + k0 + t];
                float a2 = Asf[r0 * A_STRIDE + k0 + t + 4];
                float a3 = Asf[(r0 + 8) * A_STRIDE + k0 + t + 4];
                if (CVTA) {
                    af[mf][0] = f2tf32(a0); af[mf][1] = f2tf32(a1);
                    af[mf][2] = f2tf32(a2); af[mf][3] = f2tf32(a3);
                } else {
                    af[mf][0] = __float_as_uint(a0); af[mf][1] = __float_as_uint(a1);
                    af[mf][2] = __float_as_uint(a2); af[mf][3] = __float_as_uint(a3);
                }
            }
#pragma unroll
            for (int nf = 0; nf < 4; nf++) {
                int n0 = wn * 32 + nf * 8 + g;
                bf[nf][0] = __float_as_uint(Bsf[(k0 + t) * B_STRIDE + n0]);
                bf[nf][1] = __float_as_uint(Bsf[(k0 + t + 4) * B_STRIDE + n0]);
            }
#pragma unroll
            for (int mf = 0; mf < 2; mf++)
#pragma unroll
                for (int nf = 0; nf < 4; nf++)
                    mma_tf32(acc[mf][nf], af[mf], bf[nf]);
        }

        if (st + 2 < nStages) {
            int s = (st + 2) % 3;
            int k0g = (st + 2) * 16;
            cp16(aDst + s * A_STAGE * 4, aSrc + k0g, ap);
            cp16(bDst0 + s * B_STAGE * 4, bSrc0 + (size_t)k0g * N, true);
            cp16(bDst1 + s * B_STAGE * 4, bSrc1 + (size_t)k0g * N, true);
            asm volatile("cp.async.commit_group;");
        }
    }

    if (!FUSE) {
#pragma unroll
        for (int mf = 0; mf < 2; mf++) {
            int row0 = rowBase + wm * 32 + mf * 16 + g;
#pragma unroll
            for (int nf = 0; nf < 4; nf++) {
                int col = colBase + wn * 32 + nf * 8 + 2 * t;
                float b0 = bias ? bias[col] : 0.f;
                float b1 = bias ? bias[col + 1] : 0.f;
                if (row0 < M) {
                    float2 v = make_float2(acc[mf][nf][0] + b0, acc[mf][nf][1] + b1);
                    *(float2*)(C + (size_t)row0 * N + col) = v;
                }
                if (row0 + 8 < M) {
                    float2 v = make_float2(acc[mf][nf][2] + b0, acc[mf][nf][3] + b1);
                    *(float2*)(C + (size_t)(row0 + 8) * N + col) = v;
                }
            }
        }
    } else {
        float elp[2][2] = {}, erp[2][2] = {};
#pragma unroll
        for (int nf = 0; nf < 4; nf++) {
            int col = wn * 32 + nf * 8 + 2 * t;
            float la0 = al[col], la1 = al[col + 1];
            float ra0 = ar[col], ra1 = ar[col + 1];
#pragma unroll
            for (int mf = 0; mf < 2; mf++) {
                elp[mf][0] += acc[mf][nf][0] * la0 + acc[mf][nf][1] * la1;
                elp[mf][1] += acc[mf][nf][2] * la0 + acc[mf][nf][3] * la1;
                erp[mf][0] += acc[mf][nf][0] * ra0 + acc[mf][nf][1] * ra1;
                erp[mf][1] += acc[mf][nf][2] * ra0 + acc[mf][nf][3] * ra1;
                int row0 = rowBase + wm * 32 + mf * 16 + g;
                if (row0 < M) {
                    __half2 hv = __floats2half2_rn(acc[mf][nf][0], acc[mf][nf][1]);
                    *(__half2*)(g_Whh + (size_t)row0 * DHID + col) = hv;
                }
                if (row0 + 8 < M) {
                    __half2 hv = __floats2half2_rn(acc[mf][nf][2], acc[mf][nf][3]);
                    *(__half2*)(g_Whh + (size_t)(row0 + 8) * DHID + col) = hv;
                }
            }
        }
#pragma unroll
        for (int mf = 0; mf < 2; mf++)
#pragma unroll
            for (int rh = 0; rh < 2; rh++) {
                float v = elp[mf][rh];
                v += __shfl_xor_sync(0xFFFFFFFFu, v, 1);
                v += __shfl_xor_sync(0xFFFFFFFFu, v, 2);
                elp[mf][rh] = v;
                float w = erp[mf][rh];
                w += __shfl_xor_sync(0xFFFFFFFFu, w, 1);
                w += __shfl_xor_sync(0xFFFFFFFFu, w, 2);
                erp[mf][rh] = w;
            }
        if (t == 0) {
#pragma unroll
            for (int mf = 0; mf < 2; mf++)
#pragma unroll
                for (int rh = 0; rh < 2; rh++) {
                    int gr = rowBase + wm * 32 + mf * 16 + g + rh * 8;
                    if (gr < M) {
                        g_el[gr * NH + wn] = elp[mf][rh];
                        g_er[gr * NH + wn] = erp[mf][rh];
                    }
                }
        }
    }
}

// ---------------- streams/events + func attrs ----------------
static cudaStream_t g_s2, g_s3;
static cudaEvent_t g_evFork, g_evCsr, g_evW1, g_evW2p;
struct HostInit {
    HostInit() {
        cudaStreamCreateWithFlags(&g_s2, cudaStreamNonBlocking);
        cudaStreamCreateWithFlags(&g_s3, cudaStreamNonBlocking);
        cudaEventCreateWithFlags(&g_evFork, cudaEventDisableTiming);
        cudaEventCreateWithFlags(&g_evCsr, cudaEventDisableTiming);
        cudaEventCreateWithFlags(&g_evW1, cudaEventDisableTiming);
        cudaEventCreateWithFlags(&g_evW2p, cudaEventDisableTiming);
        cudaFuncSetAttribute((const void*)gemm_tc<0, 0>, cudaFuncAttributeMaxDynamicSharedMemorySize, SMEM_BYTES);
        cudaFuncSetAttribute((const void*)gemm_tc<1, 0>, cudaFuncAttributeMaxDynamicSharedMemorySize, SMEM_BYTES);
        cudaFuncSetAttribute((const void*)gemm_tc<1, 1>, cudaFuncAttributeMaxDynamicSharedMemorySize, SMEM_BYTES);
    }
};
static HostInit g_hostInit;

// ================= CSR build (8 edges/thread, epos-based) =================
__global__ void k_count(const int4* __restrict__ dst4) {
    int i = blockIdx.x * blockDim.x + threadIdx.x;
    if (i >= NE / 8) return;
    int4 d0 = dst4[2 * i], d1 = dst4[2 * i + 1];
    int4 p0, p1;
    p0.x = atomicAdd(&g_cnt[d0.x], 1);
    p0.y = atomicAdd(&g_cnt[d0.y], 1);
    p0.z = atomicAdd(&g_cnt[d0.z], 1);
    p0.w = atomicAdd(&g_cnt[d0.w], 1);
    p1.x = atomicAdd(&g_cnt[d1.x], 1);
    p1.y = atomicAdd(&g_cnt[d1.y], 1);
    p1.z = atomicAdd(&g_cnt[d1.z], 1);
    p1.w = atomicAdd(&g_cnt[d1.w], 1);
    ((int4*)g_epos)[2 * i] = p0;
    ((int4*)g_epos)[2 * i + 1] = p1;
}

// ---- 2-phase parallel exclusive scan over g_cnt -> g_rowptr ----
__global__ void k_scan1() {
    __shared__ int wsum[SCAN_T / 32];
    int t = blockIdx.x * SCAN_T + threadIdx.x;
    int lo = t * SCAN_CH;
    int hi = lo + SCAN_CH; if (hi > NN) hi = NN;
    int s = 0;
    for (int i = lo; i < hi && lo < NN; i++) s += g_cnt[i];
    int lane = threadIdx.x & 31, w = threadIdx.x >> 5;
#pragma unroll
    for (int o = 16; o > 0; o >>= 1) s += __shfl_down_sync(0xFFFFFFFFu, s, o);
    if (lane == 0) wsum[w] = s;
    __syncthreads();
    if (threadIdx.x == 0) {
        int tot = 0;
#pragma unroll
        for (int i = 0; i < SCAN_T / 32; i++) tot += wsum[i];
        g_bsum[blockIdx.x] = tot;
    }
}

// phase 2: each block redundantly scans the 98 block sums for its own offset,
// then does its local scan, writes rowptr, and re-zeroes g_cnt.
__global__ void k_scan3() {
    __shared__ int wpref[SCAN_T / 32];
    __shared__ int blockOff;
    __shared__ int totalSum;
    int tIn = threadIdx.x;

    // warp 0 computes this block's exclusive offset over g_bsum
    if (tIn < 32) {
        int acc0 = 0, tot = 0;
        for (int b0 = 0; b0 < SCAN_BLOCKS; b0 += 32) {
            int idx = b0 + tIn;
            int v = (idx < SCAN_BLOCKS) ? g_bsum[idx] : 0;
            int incl = v;
#pragma unroll
            for (int o = 1; o < 32; o <<= 1) {
                int u = __shfl_up_sync(0xFFFFFFFFu, incl, o);
                if (tIn >= o) incl += u;
            }
            int chunkTot = __shfl_sync(0xFFFFFFFFu, incl, 31);
            // exclusive prefix of this block within chunk
            if (idx == (int)blockIdx.x) blockOff = acc0 + incl - v;
            acc0 += chunkTot;
            tot = acc0;
        }
        if (tIn == 0) totalSum = tot;
    }
    __syncthreads();

    int t = blockIdx.x * SCAN_T + tIn;
    int lo = t * SCAN_CH;
    int hi = lo + SCAN_CH; if (hi > NN) hi = NN;
    int c[SCAN_CH];
    int s = 0;
    int cntv = (lo < NN) ? (hi - lo) : 0;
    for (int i = 0; i < cntv; i++) { c[i] = g_cnt[lo + i]; s += c[i]; }
    int lane = tIn & 31, w = tIn >> 5;
    int incl = s;
#pragma unroll
    for (int o = 1; o < 32; o <<= 1) {
        int u = __shfl_up_sync(0xFFFFFFFFu, incl, o);
        if (lane >= o) incl += u;
    }
    if (lane == 31) wpref[w] = incl;
    __syncthreads();
    int woff = 0;
    for (int i = 0; i < w; i++) woff += wpref[i];
    int run = blockOff + woff + incl - s;
    for (int i = 0; i < cntv; i++) {
        g_rowptr[lo + i] = run;
        run += c[i];
        g_cnt[lo + i] = 0;          // re-zero for next graph replay
    }
    if (blockIdx.x == 0 && tIn == 0) g_rowptr[NN] = totalSum;
}

__global__ void k_fill(const int4* __restrict__ src4, const int4* __restrict__ dst4) {
    int i = blockIdx.x * blockDim.x + threadIdx.x;
    if (i >= NE / 8) return;
    int4 s0 = src4[2 * i], s1 = src4[2 * i + 1];
    int4 d0 = dst4[2 * i], d1 = dst4[2 * i + 1];
    int4 p0 = ((const int4*)g_epos)[2 * i];
    int4 p1 = ((const int4*)g_epos)[2 * i + 1];
    g_csrc[g_rowptr[d0.x] + p0.x] = s0.x;
    g_csrc[g_rowptr[d0.y] + p0.y] = s0.y;
    g_csrc[g_rowptr[d0.z] + p0.z] = s0.z;
    g_csrc[g_rowptr[d0.w] + p0.w] = s0.w;
    g_csrc[g_rowptr[d1.x] + p1.x] = s1.x;
    g_csrc[g_rowptr[d1.y] + p1.y] = s1.y;
    g_csrc[g_rowptr[d1.z] + p1.z] = s1.z;
    g_csrc[g_rowptr[d1.w] + p1.w] = s1.w;
}

// ================= fused softmax + aggregate (R7/R12 form) ====
template <int LAYER>
__global__ void k_gat_agg(const float* __restrict__ bias) {
    __shared__ float exsAll[8][128];
    int wIn = threadIdx.x >> 5;
    int n = (blockIdx.x << 3) + wIn;
    if (n >= NN) return;
    float* exsw = exsAll[wIn];
    int lane = threadIdx.x & 31;
    int myh = lane >> 3;
    int beg = g_rowptr[n], end = g_rowptr[n + 1];
    float4 er4 = *(const float4*)(g_er + n * NH);

    float ax = 0.f, ay = 0.f, az = 0.f, aw = 0.f;
    float se0 = 0.f, se1 = 0.f, se2 = 0.f, se3 = 0.f;
    const __half* WhBase = g_Whh + (size_t)(lane * 4);

    for (int base = beg; base < end; base += 32) {
        int cnt = end - base; if (cnt > 32) cnt = 32;
        int sv = 0;
        float4 elv = make_float4(0.f, 0.f, 0.f, 0.f);
        if (lane < cnt) {
            sv = g_csrc[base + lane];
            elv = *(const float4*)(g_el + sv * NH);
        }
        float e0 = __expf(lrelu(elv.x + er4.x));
        float e1 = __expf(lrelu(elv.y + er4.y));
        float e2 = __expf(lrelu(elv.z + er4.z));
        float e3 = __expf(lrelu(elv.w + er4.w));
        if (lane >= cnt) { e0 = e1 = e2 = e3 = 0.f; }
        se0 += e0; se1 += e1; se2 += e2; se3 += e3;
        __syncwarp();
        *(float4*)&exsw[lane * 4] = make_float4(e0, e1, e2, e3);
        __syncwarp();
#pragma unroll 8
        for (int j = 0; j < cnt; j++) {
            int s = __shfl_sync(0xFFFFFFFFu, sv, j);
            float exh = exsw[j * 4 + myh];
            uint2 u = *(const uint2*)(WhBase + (size_t)s * DHID);
            float2 f0 = __half22float2(*(__half2*)&u.x);
            float2 f1 = __half22float2(*(__half2*)&u.y);
            ax = fmaf(exh, f0.x, ax);
            ay = fmaf(exh, f0.y, ay);
            az = fmaf(exh, f1.x, az);
            aw = fmaf(exh, f1.y, aw);
        }
    }
#pragma unroll
    for (int o = 16; o > 0; o >>= 1) {
        se0 += __shfl_xor_sync(0xFFFFFFFFu, se0, o);
        se1 += __shfl_xor_sync(0xFFFFFFFFu, se1, o);
        se2 += __shfl_xor_sync(0xFFFFFFFFu, se2, o);
        se3 += __shfl_xor_sync(0xFFFFFFFFu, se3, o);
    }
    float seh = myh < 2 ? (myh == 0 ? se0 : se1) : (myh == 2 ? se2 : se3);
    float r = 1.0f / (seh + EPSV);
    ax *= r; ay *= r; az *= r; aw *= r;

    if (LAYER == 1) {
        int d = lane * 4;
        float4 v;
        v.x = ax + bias[d + 0];
        v.y = ay + bias[d + 1];
        v.z = az + bias[d + 2];
        v.w = aw + bias[d + 3];
        v.x = v.x > 0.f ? v.x : (__expf(v.x) - 1.0f);
        v.y = v.y > 0.f ? v.y : (__expf(v.y) - 1.0f);
        v.z = v.z > 0.f ? v.z : (__expf(v.z) - 1.0f);
        v.w = v.w > 0.f ? v.w : (__expf(v.w) - 1.0f);
        v.x = round_tf32(v.x); v.y = round_tf32(v.y);
        v.z = round_tf32(v.z); v.w = round_tf32(v.w);
        *(float4*)(g_z + (size_t)n * DHID + d) = v;
    } else {
        int d = lane * 4;
        ax += bias[d + 0]; ay += bias[d + 1]; az += bias[d + 2]; aw += bias[d + 3];
#pragma unroll
        for (int o = 8; o <= 16; o <<= 1) {
            ax += __shfl_xor_sync(0xFFFFFFFFu, ax, o);
            ay += __shfl_xor_sync(0xFFFFFFFFu, ay, o);
            az += __shfl_xor_sync(0xFFFFFFFFu, az, o);
            aw += __shfl_xor_sync(0xFFFFFFFFu, aw, o);
        }
        if (lane < 8) {
            float4 v = make_float4(round_tf32(0.25f * ax), round_tf32(0.25f * ay),
                                   round_tf32(0.25f * az), round_tf32(0.25f * aw));
            *(float4*)(g_z2 + (size_t)n * DHEAD + lane * 4) = v;
        }
    }
}

// ================= launch =================
extern "C" void kernel_launch(void* const* d_in, const int* in_sizes, int n_in,
                              void* d_out, int out_size) {
    const float* h   = (const float*)d_in[0];
    const int*   src = (const int*)d_in[1];
    const int*   dst = (const int*)d_in[2];
    const float* W1  = (const float*)d_in[3];
    const float* al1 = (const float*)d_in[4];
    const float* ar1 = (const float*)d_in[5];
    const float* b1  = (const float*)d_in[6];
    const float* W2  = (const float*)d_in[7];
    const float* al2 = (const float*)d_in[8];
    const float* ar2 = (const float*)d_in[9];
    const float* b2  = (const float*)d_in[10];
    const float* Wp  = (const float*)d_in[11];
    const float* bp  = (const float*)d_in[12];
    float* out = (float*)d_out;

    float *p_z, *p_z2, *p_W1t, *p_W2t, *p_Wpt;
    cudaGetSymbolAddress((void**)&p_z,   g_z);
    cudaGetSymbolAddress((void**)&p_z2,  g_z2);
    cudaGetSymbolAddress((void**)&p_W1t, g_W1t);
    cudaGetSymbolAddress((void**)&p_W2t, g_W2t);
    cudaGetSymbolAddress((void**)&p_Wpt, g_Wpt);

    const int TPB = 256;
    int gEdge8 = (NE / 8 + TPB - 1) / TPB;    // 391
    int gAgg   = (NN + 7) / 8;

    dim3 gemmGrid1(1, (NN + 63) / 64);              // N=128
    dim3 gemmGridP(OUTD / 128, (NN + 63) / 64);     // N=512

    // ---- fork ----
    cudaEventRecord(g_evFork, 0);
    cudaStreamWaitEvent(g_s2, g_evFork, 0);
    cudaStreamWaitEvent(g_s3, g_evFork, 0);

    // s3: weight rounding (W1 first — GEMM1's only dependency)
    k_round_w1<<<64, 256, 0, g_s3>>>(W1);
    cudaEventRecord(g_evW1, g_s3);
    k_round_w2p<<<128, 256, 0, g_s3>>>(W2, Wp);
    cudaEventRecord(g_evW2p, g_s3);

    // s2: CSR build (g_cnt zero at entry; re-zeroed by k_scan3 each replay)
    k_count<<<gEdge8, TPB, 0, g_s2>>>((const int4*)dst);
    k_scan1<<<SCAN_BLOCKS, SCAN_T, 0, g_s2>>>();
    k_scan3<<<SCAN_BLOCKS, SCAN_T, 0, g_s2>>>();
    k_fill<<<gEdge8, TPB, 0, g_s2>>>((const int4*)src, (const int4*)dst);
    cudaEventRecord(g_evCsr, g_s2);

    // ===== layer 1 =====  (A = h: cvt at load; B = pre-rounded W1)
    cudaStreamWaitEvent(0, g_evW1, 0);
    gemm_tc<1, 1><<<gemmGrid1, 256, SMEM_BYTES>>>(h, p_W1t, nullptr, nullptr,
                                                  NN, DHID, DHID, al1, ar1);
    cudaStreamWaitEvent(0, g_evCsr, 0);   // join: agg needs CSR
    k_gat_agg<1><<<gAgg, 256>>>(b1);

    // ===== layer 2 =====  (A = pre-rounded z; B = pre-rounded W2: no cvts)
    cudaStreamWaitEvent(0, g_evW2p, 0);
    gemm_tc<1, 0><<<gemmGrid1, 256, SMEM_BYTES>>>(p_z, p_W2t, nullptr, nullptr,
                                                  NN, DHID, DHID, al2, ar2);
    k_gat_agg<2><<<gAgg, 256>>>(b2);

    // ===== projection head =====  (A = pre-rounded z2; B = pre-rounded Wp)
    gemm_tc<0, 0><<<gemmGridP, 256, SMEM_BYTES>>>(p_z2, p_Wpt, bp, out,
                                                  NN, OUTD, DHEAD, nullptr, nullptr);
}